// round 8
// baseline (speedup 1.0000x reference)
#include <cuda_runtime.h>
#include <cstddef>
#include <cstdint>

// Bidirectional 2-layer LSTM; only batch row 255 feeds the output (B -> 1).
// Round 8: R7 cluster engines with (1) signal path moved into the cluster:
// per-producer monotonic step flags in peer SMEM (st.release.cluster +
// ld.acquire.cluster local polling) replacing the L2 counter on the critical
// path, and (2) fma.rn.f32x2 packed dot (halves FFMA issue pressure).

#define TT 512
#define HD 256
#define DD 128
#define BLAST 255

// ---------------- scratch (static device memory) ----------------------------
__device__ float g_zx0[2][TT][1024];   // layer0 x-part + bias (phaseA)
__device__ float g_zx1[2][TT][1024];   // layer1 x-part + bias (helpers)
__device__ float g_h0[2][TT][HD];      // layer0 h (published for helpers)
__device__ float g_h1[2][TT][HD];      // layer1 h (for phaseC)
__device__ unsigned g_csync[4];        // L0 step counters (helpers' feed)
__device__ unsigned g_cntzx[2];        // helper zx1 counters

// fast saturating gate math (proven R5-R7)
__device__ __forceinline__ float fsig(float x) {
    return __fdividef(1.0f, 1.0f + __expf(-x));
}
__device__ __forceinline__ float ftanh(float x) {
    return 1.0f - __fdividef(2.0f, __expf(2.0f * x) + 1.0f);
}

// proven counter ops (R2/R5/R7)
__device__ __forceinline__ void rel_add(unsigned* p) {
    asm volatile("red.release.gpu.global.add.u32 [%0], 1;" :: "l"(p) : "memory");
}
__device__ __forceinline__ unsigned acq_ld(const unsigned* p) {
    unsigned v;
    asm volatile("ld.acquire.gpu.global.u32 %0, [%1];" : "=r"(v) : "l"(p) : "memory");
    return v;
}

// cluster primitives (proven R6/R7)
__device__ __forceinline__ unsigned smem_u32(const void* p) {
    return (unsigned)__cvta_generic_to_shared(p);
}
__device__ __forceinline__ unsigned mapa_rank(unsigned a, unsigned r) {
    unsigned o; asm("mapa.shared::cluster.u32 %0,%1,%2;" : "=r"(o) : "r"(a), "r"(r));
    return o;
}
__device__ __forceinline__ void st_cluster_f32(unsigned a, float v) {
    asm volatile("st.shared::cluster.f32 [%0],%1;" :: "r"(a), "f"(v) : "memory");
}
// new: flag signal path (cluster-scope release store / local acquire load)
__device__ __forceinline__ void st_rel_cluster_u32(unsigned a, unsigned v) {
    asm volatile("st.release.cluster.shared::cluster.u32 [%0],%1;"
                 :: "r"(a), "r"(v) : "memory");
}
__device__ __forceinline__ unsigned ld_acq_sh(unsigned a) {
    unsigned v;
    asm volatile("ld.acquire.cluster.shared::cta.u32 %0,[%1];"
                 : "=r"(v) : "r"(a) : "memory");
    return v;
}
__device__ __forceinline__ void cluster_sync_asm() {
    asm volatile("barrier.cluster.arrive.aligned;" ::: "memory");
    asm volatile("barrier.cluster.wait.aligned;" ::: "memory");
}

// packed f32x2 helpers
__device__ __forceinline__ unsigned long long pack2(float lo, float hi) {
    unsigned long long r; asm("mov.b64 %0,{%1,%2};" : "=l"(r) : "f"(lo), "f"(hi));
    return r;
}
__device__ __forceinline__ void fma2(unsigned long long& acc, unsigned long long a,
                                     unsigned long long b) {
    asm("fma.rn.f32x2 %0,%1,%2,%0;" : "+l"(acc) : "l"(a), "l"(b));
}
__device__ __forceinline__ float2 unpack2(unsigned long long v) {
    float2 f; asm("mov.b64 {%0,%1},%2;" : "=f"(f.x), "=f"(f.y) : "l"(v));
    return f;
}

// ---------------- Phase A (proven R5-R7) -------------------------------------
__global__ void phaseA(const float* __restrict__ x,
                       const float* __restrict__ Wf0, const float* __restrict__ bf0,
                       const float* __restrict__ Wb0, const float* __restrict__ bb0)
{
    if (blockIdx.x == 0 && threadIdx.x < 6) {
        if (threadIdx.x < 4) g_csync[threadIdx.x] = 0u;
        else g_cntzx[threadIdx.x - 4] = 0u;
    }

    const int d     = blockIdx.x >> 7;
    const int chunk = blockIdx.x & 127;
    const float* __restrict__ W    = d ? Wb0 : Wf0;
    const float* __restrict__ bias = d ? bb0 : bf0;

    __shared__ float xs[4][DD];
    const int tid = threadIdx.x;
    for (int i = tid; i < 4 * DD; i += 256) {
        int t4 = i >> 7, k = i & 127;
        int s = chunk * 4 + t4;
        int t = d ? (TT - 1 - s) : s;
        xs[t4][k] = x[(size_t)BLAST * TT * DD + (size_t)t * DD + k];
    }
    __syncthreads();

    float acc[4][4];
    #pragma unroll
    for (int j = 0; j < 4; j++) {
        float b = bias[tid + j * 256];
        #pragma unroll
        for (int t4 = 0; t4 < 4; t4++) acc[j][t4] = b;
    }
    #pragma unroll 4
    for (int k = 0; k < DD; k++) {
        float xv[4];
        #pragma unroll
        for (int t4 = 0; t4 < 4; t4++) xv[t4] = xs[t4][k];
        #pragma unroll
        for (int j = 0; j < 4; j++) {
            float w = W[k * 1024 + tid + j * 256];
            #pragma unroll
            for (int t4 = 0; t4 < 4; t4++) acc[j][t4] += xv[t4] * w;
        }
    }
    #pragma unroll
    for (int j = 0; j < 4; j++)
        #pragma unroll
        for (int t4 = 0; t4 < 4; t4++)
            g_zx0[d][chunk * 4 + t4][tid + j * 256] = acc[j][t4];
}

// ---------------- Phase B ----------------------------------------------------
// grid 64 x 256 threads, cluster (8,1,1).
//   bid 0..31 : engines. eng = bid>>3 (0:L0fw 1:L0bw 2:L1fw 3:L1bw), c = bid&7.
//   bid 32..63: helpers. d = (bid-32)>>4, hc = (bid-32)&15, 64 cols each.
__global__ void __launch_bounds__(256, 1) phaseB(
    const float* __restrict__ fw_state, const float* __restrict__ bw_state,
    const float* __restrict__ Wf0,
    const float* __restrict__ Wf1, const float* __restrict__ bf1,
    const float* __restrict__ Wb0,
    const float* __restrict__ Wb1, const float* __restrict__ bb1)
{
    __shared__ __align__(16) float hbuf[2][HD];   // h double buffer (DSMEM target)
    __shared__ float redb[2][HD];                 // partial sums (double buffer)
    __shared__ float zbuf[2][128];                // prefetched zx (double buffer)
    __shared__ float cs[32];
    __shared__ unsigned flags[8];                 // per-producer monotonic step flags

    const int bid = blockIdx.x;
    const int tid = threadIdx.x;

    if (bid < 32) {
        // ======================= cluster engine =============================
        const int eng = bid >> 3, c = bid & 7;
        const int layer = eng >> 1, d = eng & 1;
        const float* __restrict__ state = d ? bw_state : fw_state;
        const float* __restrict__ W = layer ? (d ? Wb1 : Wf1) : (d ? Wb0 : Wf0);
        const int rowbase = layer ? 256 : 128;   // recurrent rows of W

        const int p = tid >> 7;            // K half (128 rows)
        const int l = tid & 127;           // local col 0..127
        const int g = l >> 5, j = l & 31;
        const int gcol = g * 256 + c * 32 + j;

        // recurrent weights packed as (row 2i, row 2i+1) f32x2 pairs
        unsigned long long w2[64];
        #pragma unroll
        for (int i = 0; i < 64; i++) {
            const float* wp = W + (size_t)(rowbase + p * 128 + 2 * i) * 1024 + gcol;
            w2[i] = pack2(wp[0], wp[1024]);
        }

        const float* srow = state + (size_t)BLAST * 1024 + layer * 512;
        hbuf[0][tid] = srow[256 + tid];    // h_init, consumed at step 0
        if (tid < 32) cs[tid] = srow[c * 32 + tid];
        if (tid < 8) flags[tid] = 0u;

        const float* zxs = layer ? &g_zx1[d][0][0] : &g_zx0[d][0][0];
        float*       hgl = layer ? &g_h1[d][0][0]  : &g_h0[d][0][0];
        unsigned* cnt    = &g_csync[eng];
        unsigned* cntzxd = &g_cntzx[d];

        // gate warp: remote hbuf addresses (both buffers) + remote flag addrs
        unsigned rs[2][8], rf[8];
        if (tid < 32) {
            #pragma unroll
            for (int b = 0; b < 2; b++) {
                unsigned a = smem_u32(&hbuf[b][c * 32 + tid]);
                #pragma unroll
                for (int r = 0; r < 8; r++) rs[b][r] = mapa_rank(a, (unsigned)r);
            }
            unsigned fa = smem_u32(&flags[c]);
            #pragma unroll
            for (int r = 0; r < 8; r++) rf[r] = mapa_rank(fa, (unsigned)r);
        }
        const unsigned myflag = smem_u32(&flags[tid & 7]);

        // fetch warp (tid 32..63): preload zbuf[0] = zx[step 0]
        if (tid >= 32 && tid < 64) {
            const int ft = tid - 32;
            if (layer == 1) {
                if (ft == 0) { while (acq_ld(cntzxd) < 16u) { } }
                __syncwarp();
            }
            #pragma unroll
            for (int gg = 0; gg < 4; gg++)
                zbuf[0][gg * 32 + ft] = __ldcg(zxs + 0 * 1024 + gg * 256 + c * 32 + ft);
        }
        __syncthreads();
        cluster_sync_asm();    // peers resident; hbuf[0] + flags initialized

        for (int s = 0; s < TT; s++) {
            const int sb = s & 1;
            if (s > 0) {
                // wait for all 8 producers to have pushed h[s-1] (flag >= s)
                if (tid < 8) {
                    while (ld_acq_sh(myflag) < (unsigned)s) { }
                }
                __syncthreads();
            }

            // dot over K half (f32x2 packed; h local via DSMEM push)
            unsigned long long acc0 = 0ull, acc1 = 0ull;
            const float* hv = &hbuf[sb][p * 128];
            #pragma unroll
            for (int i = 0; i < 128; i += 8) {
                float4 ha = *(const float4*)&hv[i];
                float4 hb = *(const float4*)&hv[i + 4];
                fma2(acc0, w2[i / 2],     pack2(ha.x, ha.y));
                fma2(acc1, w2[i / 2 + 1], pack2(ha.z, ha.w));
                fma2(acc0, w2[i / 2 + 2], pack2(hb.x, hb.y));
                fma2(acc1, w2[i / 2 + 3], pack2(hb.z, hb.w));
            }
            float2 a0 = unpack2(acc0), a1 = unpack2(acc1);
            redb[sb][p * 128 + l] = (a0.x + a0.y) + (a1.x + a1.y);
            __syncthreads();               // dot complete CTA-wide

            if (tid < 32) {
                // gate warp
                float z[4];
                #pragma unroll
                for (int gg = 0; gg < 4; gg++)
                    z[gg] = redb[sb][gg * 32 + tid] + redb[sb][128 + gg * 32 + tid]
                          + zbuf[sb][gg * 32 + tid];
                float cn = fsig(z[2] + 1.0f) * cs[tid] + fsig(z[0]) * ftanh(z[1]);
                float hn = fsig(z[3]) * ftanh(cn);
                cs[tid] = cn;

                // push h[s] into all 8 peers' other buffer (incl. self)
                const int wb = (s + 1) & 1;
                #pragma unroll
                for (int r = 0; r < 8; r++) st_cluster_f32(rs[wb][r], hn);
                __syncwarp();
                if (tid == 0) {
                    // release-publish step flag into every peer (critical path)
                    #pragma unroll
                    for (int r = 0; r < 8; r++)
                        st_rel_cluster_u32(rf[r], (unsigned)(s + 1));
                }
                // publish to L2 (helpers for L0; phaseC for L1) — off critical path
                __stcg(hgl + (size_t)s * HD + c * 32 + tid, hn);
                __syncwarp();
                if (tid == 0 && layer == 0) rel_add(cnt);
            } else if (tid < 64) {
                // fetch warp: prefetch zx for step s+1
                if (s + 1 < TT) {
                    const int ft = tid - 32;
                    if (layer == 1) {
                        if (ft == 0) {
                            unsigned tgt = 16u * (unsigned)(s + 2);
                            while (acq_ld(cntzxd) < tgt) { }
                        }
                        __syncwarp();
                    }
                    #pragma unroll
                    for (int gg = 0; gg < 4; gg++)
                        zbuf[(s + 1) & 1][gg * 32 + ft] =
                            __ldcg(zxs + (size_t)(s + 1) * 1024 + gg * 256 + c * 32 + ft);
                }
            }
        }
        cluster_sync_asm();    // keep SMEM alive for in-flight peer stores
    } else {
        // ======================= helper CTAs (proven sync) ==================
        const int hix = bid - 32;
        const int d   = hix >> 4;
        const int hc  = hix & 15;
        const float* __restrict__ W    = d ? Wb1 : Wf1;
        const float* __restrict__ bias = d ? bb1 : bf1;
        const int p = tid >> 6;            // K quarter (64 rows of W1[0:256])
        const int l = tid & 63;            // col (64 per CTA)
        const int col = hc * 64 + l;

        float w[64];
        #pragma unroll
        for (int i = 0; i < 64; i++)
            w[i] = W[(size_t)(p * 64 + i) * 1024 + col];
        const float bb = (tid < 64) ? bias[hc * 64 + tid] : 0.0f;

        float* hs  = &hbuf[0][0];          // reuse engine smem
        float* red = &redb[0][0];
        unsigned* cnt0d  = &g_csync[d];    // L0 engine counter for this dir
        unsigned* cntzxd = &g_cntzx[d];
        const int koff = p * 64;

        for (int s = 0; s < TT; s++) {
            if (tid == 0) {
                unsigned tgt = 8u * (unsigned)(s + 1);   // 8 L0 CTAs per dir
                while (acq_ld(cnt0d) < tgt) { }
            }
            __syncthreads();
            hs[tid] = __ldcg(&g_h0[d][s][tid]);
            __syncthreads();

            float acc = 0.0f;
            #pragma unroll
            for (int i = 0; i < 64; i += 4) {
                float4 h4 = *(const float4*)&hs[koff + i];
                acc += w[i] * h4.x; acc += w[i + 1] * h4.y;
                acc += w[i + 2] * h4.z; acc += w[i + 3] * h4.w;
            }
            red[tid] = acc;
            __syncthreads();
            if (tid < 64) {
                float z = bb + red[tid] + red[64 + tid] + red[128 + tid] + red[192 + tid];
                __stcg(&g_zx1[d][s][hc * 64 + tid], z);
            }
            __syncthreads();               // all 64 stores issued before signal
            if (tid == 0) rel_add(cntzxd);
        }
    }
}

// ---------------- Phase C: final dense ---------------------------------------
__global__ void phaseC(const float* __restrict__ Wd, const float* __restrict__ bd,
                       float* __restrict__ out)
{
    const int chunk = blockIdx.x;
    const int o = threadIdx.x;
    __shared__ float hsm[8][512];
    for (int i = threadIdx.x; i < 8 * 512; i += 128) {
        int t8 = i >> 9, k = i & 511;
        int t = chunk * 8 + t8;
        hsm[t8][k] = (k < 256) ? g_h1[0][t][k] : g_h1[1][TT - 1 - t][k - 256];
    }
    __syncthreads();
    float b = bd[o];
    float acc[8];
    #pragma unroll
    for (int t8 = 0; t8 < 8; t8++) acc[t8] = b;
    #pragma unroll 8
    for (int k = 0; k < 512; k++) {
        float w = Wd[k * 128 + o];
        #pragma unroll
        for (int t8 = 0; t8 < 8; t8++) acc[t8] += hsm[t8][k] * w;
    }
    #pragma unroll
    for (int t8 = 0; t8 < 8; t8++) out[(chunk * 8 + t8) * 128 + o] = acc[t8];
}

// ---------------- launch -----------------------------------------------------
extern "C" void kernel_launch(void* const* d_in, const int* in_sizes, int n_in,
                              void* d_out, int out_size)
{
    (void)in_sizes; (void)n_in; (void)out_size;
    const float* x        = (const float*)d_in[0];
    const float* fw_state = (const float*)d_in[1];
    const float* bw_state = (const float*)d_in[2];
    const float* Wf0 = (const float*)d_in[3];
    const float* bf0 = (const float*)d_in[4];
    const float* Wf1 = (const float*)d_in[5];
    const float* bf1 = (const float*)d_in[6];
    const float* Wb0 = (const float*)d_in[7];
    const float* bb0 = (const float*)d_in[8];
    const float* Wb1 = (const float*)d_in[9];
    const float* bb1 = (const float*)d_in[10];
    const float* Wd  = (const float*)d_in[11];
    const float* bd  = (const float*)d_in[12];

    phaseA<<<256, 256>>>(x, Wf0, bf0, Wb0, bb0);

    cudaLaunchConfig_t cfg = {};
    cfg.gridDim  = dim3(64, 1, 1);
    cfg.blockDim = dim3(256, 1, 1);
    cfg.dynamicSmemBytes = 0;
    cfg.stream = 0;
    cudaLaunchAttribute attr[1];
    attr[0].id = cudaLaunchAttributeClusterDimension;
    attr[0].val.clusterDim.x = 8;
    attr[0].val.clusterDim.y = 1;
    attr[0].val.clusterDim.z = 1;
    cfg.attrs = attr;
    cfg.numAttrs = 1;
    cudaLaunchKernelEx(&cfg, phaseB, fw_state, bw_state,
                       Wf0, Wf1, bf1, Wb0, Wb1, bb1);

    phaseC<<<64, 128>>>(Wd, bd, (float*)d_out);
}

// round 9
// speedup vs baseline: 1.6985x; 1.6985x over previous
#include <cuda_runtime.h>
#include <cstddef>
#include <cstdint>

// Bidirectional 2-layer LSTM; only batch row 255 feeds the output (B -> 1).
// Round 9: R7 base (882.8us, proven) with ONE delta: per-step engine sync via
// split hardware cluster barrier (arrive after DSMEM h-push, wait before dot)
// replacing the L2 counter poll on the critical path. Counters remain only on
// off-critical-path edges (L0 -> helpers -> L1 fetch warp).

#define TT 512
#define HD 256
#define DD 128
#define BLAST 255

// ---------------- scratch (static device memory) ----------------------------
__device__ float g_zx0[2][TT][1024];   // layer0 x-part + bias (phaseA)
__device__ float g_zx1[2][TT][1024];   // layer1 x-part + bias (helpers)
__device__ float g_h0[2][TT][HD];      // layer0 h (published for helpers)
__device__ float g_h1[2][TT][HD];      // layer1 h (for phaseC)
__device__ unsigned g_csync[4];        // L0 step counters (helpers' feed)
__device__ unsigned g_cntzx[2];        // helper zx1 counters

// fast saturating gate math (proven R5-R8)
__device__ __forceinline__ float fsig(float x) {
    return __fdividef(1.0f, 1.0f + __expf(-x));
}
__device__ __forceinline__ float ftanh(float x) {
    return 1.0f - __fdividef(2.0f, __expf(2.0f * x) + 1.0f);
}

// proven counter ops (R2/R5/R7)
__device__ __forceinline__ void rel_add(unsigned* p) {
    asm volatile("red.release.gpu.global.add.u32 [%0], 1;" :: "l"(p) : "memory");
}
__device__ __forceinline__ unsigned acq_ld(const unsigned* p) {
    unsigned v;
    asm volatile("ld.acquire.gpu.global.u32 %0, [%1];" : "=r"(v) : "l"(p) : "memory");
    return v;
}

// cluster primitives (proven R6/R7)
__device__ __forceinline__ unsigned smem_u32(const void* p) {
    return (unsigned)__cvta_generic_to_shared(p);
}
__device__ __forceinline__ unsigned mapa_rank(unsigned a, unsigned r) {
    unsigned o; asm("mapa.shared::cluster.u32 %0,%1,%2;" : "=r"(o) : "r"(a), "r"(r));
    return o;
}
__device__ __forceinline__ void st_cluster_f32(unsigned a, float v) {
    asm volatile("st.shared::cluster.f32 [%0],%1;" :: "r"(a), "f"(v) : "memory");
}
__device__ __forceinline__ void cluster_arrive() {
    asm volatile("barrier.cluster.arrive.aligned;" ::: "memory");
}
__device__ __forceinline__ void cluster_wait() {
    asm volatile("barrier.cluster.wait.aligned;" ::: "memory");
}
__device__ __forceinline__ void cluster_sync_asm() {
    asm volatile("barrier.cluster.arrive.aligned;" ::: "memory");
    asm volatile("barrier.cluster.wait.aligned;" ::: "memory");
}

// ---------------- Phase A (proven R5-R8) -------------------------------------
__global__ void phaseA(const float* __restrict__ x,
                       const float* __restrict__ Wf0, const float* __restrict__ bf0,
                       const float* __restrict__ Wb0, const float* __restrict__ bb0)
{
    if (blockIdx.x == 0 && threadIdx.x < 6) {
        if (threadIdx.x < 4) g_csync[threadIdx.x] = 0u;
        else g_cntzx[threadIdx.x - 4] = 0u;
    }

    const int d     = blockIdx.x >> 7;
    const int chunk = blockIdx.x & 127;
    const float* __restrict__ W    = d ? Wb0 : Wf0;
    const float* __restrict__ bias = d ? bb0 : bf0;

    __shared__ float xs[4][DD];
    const int tid = threadIdx.x;
    for (int i = tid; i < 4 * DD; i += 256) {
        int t4 = i >> 7, k = i & 127;
        int s = chunk * 4 + t4;
        int t = d ? (TT - 1 - s) : s;
        xs[t4][k] = x[(size_t)BLAST * TT * DD + (size_t)t * DD + k];
    }
    __syncthreads();

    float acc[4][4];
    #pragma unroll
    for (int j = 0; j < 4; j++) {
        float b = bias[tid + j * 256];
        #pragma unroll
        for (int t4 = 0; t4 < 4; t4++) acc[j][t4] = b;
    }
    #pragma unroll 4
    for (int k = 0; k < DD; k++) {
        float xv[4];
        #pragma unroll
        for (int t4 = 0; t4 < 4; t4++) xv[t4] = xs[t4][k];
        #pragma unroll
        for (int j = 0; j < 4; j++) {
            float w = W[k * 1024 + tid + j * 256];
            #pragma unroll
            for (int t4 = 0; t4 < 4; t4++) acc[j][t4] += xv[t4] * w;
        }
    }
    #pragma unroll
    for (int j = 0; j < 4; j++)
        #pragma unroll
        for (int t4 = 0; t4 < 4; t4++)
            g_zx0[d][chunk * 4 + t4][tid + j * 256] = acc[j][t4];
}

// ---------------- Phase B ----------------------------------------------------
// grid 64 x 256 threads, cluster (8,1,1).
//   bid 0..31 : engines. eng = bid>>3 (0:L0fw 1:L0bw 2:L1fw 3:L1bw), c = bid&7.
//   bid 32..63: helpers. d = (bid-32)>>4, hc = (bid-32)&15, 64 cols each.
__global__ void __launch_bounds__(256, 1) phaseB(
    const float* __restrict__ fw_state, const float* __restrict__ bw_state,
    const float* __restrict__ Wf0,
    const float* __restrict__ Wf1, const float* __restrict__ bf1,
    const float* __restrict__ Wb0,
    const float* __restrict__ Wb1, const float* __restrict__ bb1)
{
    __shared__ __align__(16) float hbuf[2][HD];   // h double buffer (DSMEM target)
    __shared__ float redb[2][HD];                 // partial sums (double buffer)
    __shared__ float zbuf[2][128];                // prefetched zx (double buffer)
    __shared__ float cs[32];

    const int bid = blockIdx.x;
    const int tid = threadIdx.x;

    if (bid < 32) {
        // ======================= cluster engine =============================
        const int eng = bid >> 3, c = bid & 7;
        const int layer = eng >> 1, d = eng & 1;
        const float* __restrict__ state = d ? bw_state : fw_state;
        const float* __restrict__ W = layer ? (d ? Wb1 : Wf1) : (d ? Wb0 : Wf0);
        const int rowbase = layer ? 256 : 128;   // recurrent rows of W

        const int p = tid >> 7;            // K half (128 rows)
        const int l = tid & 127;           // local col 0..127
        const int g = l >> 5, j = l & 31;
        const int gcol = g * 256 + c * 32 + j;

        float w[128];                      // recurrent weights, registers
        #pragma unroll
        for (int i = 0; i < 128; i++)
            w[i] = W[(size_t)(rowbase + p * 128 + i) * 1024 + gcol];

        const float* srow = state + (size_t)BLAST * 1024 + layer * 512;
        hbuf[0][tid] = srow[256 + tid];    // h_init, consumed at step 0
        if (tid < 32) cs[tid] = srow[c * 32 + tid];

        const float* zxs = layer ? &g_zx1[d][0][0] : &g_zx0[d][0][0];
        float*       hgl = layer ? &g_h1[d][0][0]  : &g_h0[d][0][0];
        unsigned* cnt    = &g_csync[eng];
        unsigned* cntzxd = &g_cntzx[d];

        // gate warp: precompute remote hbuf addresses (both buffers x 8 ranks)
        unsigned rs[2][8];
        if (tid < 32) {
            #pragma unroll
            for (int b = 0; b < 2; b++) {
                unsigned a = smem_u32(&hbuf[b][c * 32 + tid]);
                #pragma unroll
                for (int r = 0; r < 8; r++) rs[b][r] = mapa_rank(a, (unsigned)r);
            }
        }
        // fetch warp (tid 32..63): preload zbuf[0] = zx[step 0]
        if (tid >= 32 && tid < 64) {
            const int ft = tid - 32;
            if (layer == 1) {
                if (ft == 0) { while (acq_ld(cntzxd) < 16u) { } }
                __syncwarp();
            }
            #pragma unroll
            for (int gg = 0; gg < 4; gg++)
                zbuf[0][gg * 32 + ft] = __ldcg(zxs + 0 * 1024 + gg * 256 + c * 32 + ft);
        }
        __syncthreads();
        cluster_sync_asm();    // all peers resident + hbuf[0] initialized

        for (int s = 0; s < TT; s++) {
            const int sb = s & 1;
            // wait pairs with all peers' arrive from step s-1: h[s-1] visible
            if (s > 0) cluster_wait();

            // dot over K half (h[s-1] already local via DSMEM push)
            float acc = 0.0f;
            const float* hv = &hbuf[sb][p * 128];
            #pragma unroll
            for (int i = 0; i < 128; i += 4) {
                float4 h4 = *(const float4*)&hv[i];
                acc += w[i] * h4.x; acc += w[i + 1] * h4.y;
                acc += w[i + 2] * h4.z; acc += w[i + 3] * h4.w;
            }
            redb[sb][p * 128 + l] = acc;
            __syncthreads();               // dot complete CTA-wide

            if (tid < 32) {
                // gate warp
                float z[4];
                #pragma unroll
                for (int gg = 0; gg < 4; gg++)
                    z[gg] = redb[sb][gg * 32 + tid] + redb[sb][128 + gg * 32 + tid]
                          + zbuf[sb][gg * 32 + tid];
                float cn = fsig(z[2] + 1.0f) * cs[tid] + fsig(z[0]) * ftanh(z[1]);
                float hn = fsig(z[3]) * ftanh(cn);
                cs[tid] = cn;

                // push h[s] into all 8 peers' other buffer (incl. self);
                // the cluster arrive below (release) publishes these stores
                const int wb = (s + 1) & 1;
                #pragma unroll
                for (int r = 0; r < 8; r++) st_cluster_f32(rs[wb][r], hn);
                // publish to L2 (helpers for L0; phaseC for L1)
                __stcg(hgl + (size_t)s * HD + c * 32 + tid, hn);
                __syncwarp();
                if (tid == 0 && layer == 0) rel_add(cnt);
            } else if (tid < 64) {
                // fetch warp: prefetch zx for step s+1
                if (s + 1 < TT) {
                    const int ft = tid - 32;
                    if (layer == 1) {
                        if (ft == 0) {
                            unsigned tgt = 16u * (unsigned)(s + 2);
                            while (acq_ld(cntzxd) < tgt) { }
                        }
                        __syncwarp();
                    }
                    #pragma unroll
                    for (int gg = 0; gg < 4; gg++)
                        zbuf[(s + 1) & 1][gg * 32 + ft] =
                            __ldcg(zxs + (size_t)(s + 1) * 1024 + gg * 256 + c * 32 + ft);
                }
            }
            // arrive for step s (gate lanes arrive after their pushes)
            if (s < TT - 1) cluster_arrive();
        }
        cluster_sync_asm();    // keep SMEM alive for in-flight peer stores
    } else {
        // ======================= helper CTAs (proven sync) ==================
        const int hix = bid - 32;
        const int d   = hix >> 4;
        const int hc  = hix & 15;
        const float* __restrict__ W    = d ? Wb1 : Wf1;
        const float* __restrict__ bias = d ? bb1 : bf1;
        const int p = tid >> 6;            // K quarter (64 rows of W1[0:256])
        const int l = tid & 63;            // col (64 per CTA)
        const int col = hc * 64 + l;

        float w[64];
        #pragma unroll
        for (int i = 0; i < 64; i++)
            w[i] = W[(size_t)(p * 64 + i) * 1024 + col];
        const float bb = (tid < 64) ? bias[hc * 64 + tid] : 0.0f;

        float* hs  = &hbuf[0][0];          // reuse engine smem
        float* red = &redb[0][0];
        unsigned* cnt0d  = &g_csync[d];    // L0 engine counter for this dir
        unsigned* cntzxd = &g_cntzx[d];
        const int koff = p * 64;

        for (int s = 0; s < TT; s++) {
            if (tid == 0) {
                unsigned tgt = 8u * (unsigned)(s + 1);   // 8 L0 CTAs per dir
                while (acq_ld(cnt0d) < tgt) { }
            }
            __syncthreads();
            hs[tid] = __ldcg(&g_h0[d][s][tid]);
            __syncthreads();

            float acc = 0.0f;
            #pragma unroll
            for (int i = 0; i < 64; i += 4) {
                float4 h4 = *(const float4*)&hs[koff + i];
                acc += w[i] * h4.x; acc += w[i + 1] * h4.y;
                acc += w[i + 2] * h4.z; acc += w[i + 3] * h4.w;
            }
            red[tid] = acc;
            __syncthreads();
            if (tid < 64) {
                float z = bb + red[tid] + red[64 + tid] + red[128 + tid] + red[192 + tid];
                __stcg(&g_zx1[d][s][hc * 64 + tid], z);
            }
            __syncthreads();               // all 64 stores issued before signal
            if (tid == 0) rel_add(cntzxd);
        }
    }
}

// ---------------- Phase C: final dense ---------------------------------------
__global__ void phaseC(const float* __restrict__ Wd, const float* __restrict__ bd,
                       float* __restrict__ out)
{
    const int chunk = blockIdx.x;
    const int o = threadIdx.x;
    __shared__ float hsm[8][512];
    for (int i = threadIdx.x; i < 8 * 512; i += 128) {
        int t8 = i >> 9, k = i & 511;
        int t = chunk * 8 + t8;
        hsm[t8][k] = (k < 256) ? g_h1[0][t][k] : g_h1[1][TT - 1 - t][k - 256];
    }
    __syncthreads();
    float b = bd[o];
    float acc[8];
    #pragma unroll
    for (int t8 = 0; t8 < 8; t8++) acc[t8] = b;
    #pragma unroll 8
    for (int k = 0; k < 512; k++) {
        float w = Wd[k * 128 + o];
        #pragma unroll
        for (int t8 = 0; t8 < 8; t8++) acc[t8] += hsm[t8][k] * w;
    }
    #pragma unroll
    for (int t8 = 0; t8 < 8; t8++) out[(chunk * 8 + t8) * 128 + o] = acc[t8];
}

// ---------------- launch -----------------------------------------------------
extern "C" void kernel_launch(void* const* d_in, const int* in_sizes, int n_in,
                              void* d_out, int out_size)
{
    (void)in_sizes; (void)n_in; (void)out_size;
    const float* x        = (const float*)d_in[0];
    const float* fw_state = (const float*)d_in[1];
    const float* bw_state = (const float*)d_in[2];
    const float* Wf0 = (const float*)d_in[3];
    const float* bf0 = (const float*)d_in[4];
    const float* Wf1 = (const float*)d_in[5];
    const float* bf1 = (const float*)d_in[6];
    const float* Wb0 = (const float*)d_in[7];
    const float* bb0 = (const float*)d_in[8];
    const float* Wb1 = (const float*)d_in[9];
    const float* bb1 = (const float*)d_in[10];
    const float* Wd  = (const float*)d_in[11];
    const float* bd  = (const float*)d_in[12];

    phaseA<<<256, 256>>>(x, Wf0, bf0, Wb0, bb0);

    cudaLaunchConfig_t cfg = {};
    cfg.gridDim  = dim3(64, 1, 1);
    cfg.blockDim = dim3(256, 1, 1);
    cfg.dynamicSmemBytes = 0;
    cfg.stream = 0;
    cudaLaunchAttribute attr[1];
    attr[0].id = cudaLaunchAttributeClusterDimension;
    attr[0].val.clusterDim.x = 8;
    attr[0].val.clusterDim.y = 1;
    attr[0].val.clusterDim.z = 1;
    cfg.attrs = attr;
    cfg.numAttrs = 1;
    cudaLaunchKernelEx(&cfg, phaseB, fw_state, bw_state,
                       Wf0, Wf1, bf1, Wb0, Wb1, bb1);

    phaseC<<<64, 128>>>(Wd, bd, (float*)d_out);
}

// round 10
// speedup vs baseline: 1.7112x; 1.0075x over previous
#include <cuda_runtime.h>
#include <cstddef>
#include <cstdint>

// Bidirectional 2-layer LSTM; only batch row 255 feeds the output (B -> 1).
// Round 10: R9 cluster engines with two measured-and-salvaged deltas:
//  (1) f32x2 packed dot (correctness-proven in R8),
//  (2) DSMEM flag sync done right: ONE fence.acq_rel.cluster + 8 parallel plain
//      remote flag stores (R8's correctness, without its 8 serial release fences),
//      replacing the ~490-cyc cluster barrier on the critical path.

#define TT 512
#define HD 256
#define DD 128
#define BLAST 255

// ---------------- scratch (static device memory) ----------------------------
__device__ float g_zx0[2][TT][1024];   // layer0 x-part + bias (phaseA)
__device__ float g_zx1[2][TT][1024];   // layer1 x-part + bias (helpers)
__device__ float g_h0[2][TT][HD];      // layer0 h (published for helpers)
__device__ float g_h1[2][TT][HD];      // layer1 h (for phaseC)
__device__ unsigned g_csync[4];        // L0 step counters (helpers' feed)
__device__ unsigned g_cntzx[2];        // helper zx1 counters

// fast saturating gate math (proven R5-R9)
__device__ __forceinline__ float fsig(float x) {
    return __fdividef(1.0f, 1.0f + __expf(-x));
}
__device__ __forceinline__ float ftanh(float x) {
    return 1.0f - __fdividef(2.0f, __expf(2.0f * x) + 1.0f);
}

// proven counter ops (R2/R5/R7/R9)
__device__ __forceinline__ void rel_add(unsigned* p) {
    asm volatile("red.release.gpu.global.add.u32 [%0], 1;" :: "l"(p) : "memory");
}
__device__ __forceinline__ unsigned acq_ld(const unsigned* p) {
    unsigned v;
    asm volatile("ld.acquire.gpu.global.u32 %0, [%1];" : "=r"(v) : "l"(p) : "memory");
    return v;
}

// cluster primitives (proven R6-R9)
__device__ __forceinline__ unsigned smem_u32(const void* p) {
    return (unsigned)__cvta_generic_to_shared(p);
}
__device__ __forceinline__ unsigned mapa_rank(unsigned a, unsigned r) {
    unsigned o; asm("mapa.shared::cluster.u32 %0,%1,%2;" : "=r"(o) : "r"(a), "r"(r));
    return o;
}
__device__ __forceinline__ void st_cluster_f32(unsigned a, float v) {
    asm volatile("st.shared::cluster.f32 [%0],%1;" :: "r"(a), "f"(v) : "memory");
}
__device__ __forceinline__ void st_cluster_u32(unsigned a, unsigned v) {
    asm volatile("st.shared::cluster.u32 [%0],%1;" :: "r"(a), "r"(v) : "memory");
}
__device__ __forceinline__ void fence_acqrel_cluster() {
    asm volatile("fence.acq_rel.cluster;" ::: "memory");
}
__device__ __forceinline__ unsigned ld_acq_sh(unsigned a) {
    unsigned v;
    asm volatile("ld.acquire.cluster.shared::cta.u32 %0,[%1];"
                 : "=r"(v) : "r"(a) : "memory");
    return v;
}
__device__ __forceinline__ void cluster_sync_asm() {
    asm volatile("barrier.cluster.arrive.aligned;" ::: "memory");
    asm volatile("barrier.cluster.wait.aligned;" ::: "memory");
}

// packed f32x2 helpers (correctness-proven R8)
__device__ __forceinline__ unsigned long long pack2(float lo, float hi) {
    unsigned long long r; asm("mov.b64 %0,{%1,%2};" : "=l"(r) : "f"(lo), "f"(hi));
    return r;
}
__device__ __forceinline__ void fma2(unsigned long long& acc, unsigned long long a,
                                     unsigned long long b) {
    asm("fma.rn.f32x2 %0,%1,%2,%0;" : "+l"(acc) : "l"(a), "l"(b));
}
__device__ __forceinline__ float2 unpack2(unsigned long long v) {
    float2 f; asm("mov.b64 {%0,%1},%2;" : "=f"(f.x), "=f"(f.y) : "l"(v));
    return f;
}

// ---------------- Phase A (proven R5-R9) -------------------------------------
__global__ void phaseA(const float* __restrict__ x,
                       const float* __restrict__ Wf0, const float* __restrict__ bf0,
                       const float* __restrict__ Wb0, const float* __restrict__ bb0)
{
    if (blockIdx.x == 0 && threadIdx.x < 6) {
        if (threadIdx.x < 4) g_csync[threadIdx.x] = 0u;
        else g_cntzx[threadIdx.x - 4] = 0u;
    }

    const int d     = blockIdx.x >> 7;
    const int chunk = blockIdx.x & 127;
    const float* __restrict__ W    = d ? Wb0 : Wf0;
    const float* __restrict__ bias = d ? bb0 : bf0;

    __shared__ float xs[4][DD];
    const int tid = threadIdx.x;
    for (int i = tid; i < 4 * DD; i += 256) {
        int t4 = i >> 7, k = i & 127;
        int s = chunk * 4 + t4;
        int t = d ? (TT - 1 - s) : s;
        xs[t4][k] = x[(size_t)BLAST * TT * DD + (size_t)t * DD + k];
    }
    __syncthreads();

    float acc[4][4];
    #pragma unroll
    for (int j = 0; j < 4; j++) {
        float b = bias[tid + j * 256];
        #pragma unroll
        for (int t4 = 0; t4 < 4; t4++) acc[j][t4] = b;
    }
    #pragma unroll 4
    for (int k = 0; k < DD; k++) {
        float xv[4];
        #pragma unroll
        for (int t4 = 0; t4 < 4; t4++) xv[t4] = xs[t4][k];
        #pragma unroll
        for (int j = 0; j < 4; j++) {
            float w = W[k * 1024 + tid + j * 256];
            #pragma unroll
            for (int t4 = 0; t4 < 4; t4++) acc[j][t4] += xv[t4] * w;
        }
    }
    #pragma unroll
    for (int j = 0; j < 4; j++)
        #pragma unroll
        for (int t4 = 0; t4 < 4; t4++)
            g_zx0[d][chunk * 4 + t4][tid + j * 256] = acc[j][t4];
}

// ---------------- Phase B ----------------------------------------------------
// grid 64 x 256 threads, cluster (8,1,1).
//   bid 0..31 : engines. eng = bid>>3 (0:L0fw 1:L0bw 2:L1fw 3:L1bw), c = bid&7.
//   bid 32..63: helpers. d = (bid-32)>>4, hc = (bid-32)&15, 64 cols each.
__global__ void __launch_bounds__(256, 1) phaseB(
    const float* __restrict__ fw_state, const float* __restrict__ bw_state,
    const float* __restrict__ Wf0,
    const float* __restrict__ Wf1, const float* __restrict__ bf1,
    const float* __restrict__ Wb0,
    const float* __restrict__ Wb1, const float* __restrict__ bb1)
{
    __shared__ __align__(16) float hbuf[2][HD];   // h double buffer (DSMEM target)
    __shared__ float redb[2][HD];                 // partial sums (double buffer)
    __shared__ float zbuf[2][128];                // prefetched zx (double buffer)
    __shared__ float cs[32];
    __shared__ unsigned flags[8];                 // per-producer monotonic step flags

    const int bid = blockIdx.x;
    const int tid = threadIdx.x;

    if (bid < 32) {
        // ======================= cluster engine =============================
        const int eng = bid >> 3, c = bid & 7;
        const int layer = eng >> 1, d = eng & 1;
        const float* __restrict__ state = d ? bw_state : fw_state;
        const float* __restrict__ W = layer ? (d ? Wb1 : Wf1) : (d ? Wb0 : Wf0);
        const int rowbase = layer ? 256 : 128;   // recurrent rows of W

        const int p = tid >> 7;            // K half (128 rows)
        const int l = tid & 127;           // local col 0..127
        const int g = l >> 5, j = l & 31;
        const int gcol = g * 256 + c * 32 + j;

        // recurrent weights packed as (row 2i, row 2i+1) f32x2 pairs (R8-proven)
        unsigned long long w2[64];
        #pragma unroll
        for (int i = 0; i < 64; i++) {
            const float* wp = W + (size_t)(rowbase + p * 128 + 2 * i) * 1024 + gcol;
            w2[i] = pack2(wp[0], wp[1024]);
        }

        const float* srow = state + (size_t)BLAST * 1024 + layer * 512;
        hbuf[0][tid] = srow[256 + tid];    // h_init, consumed at step 0
        if (tid < 32) cs[tid] = srow[c * 32 + tid];
        if (tid < 8) flags[tid] = 0u;

        const float* zxs = layer ? &g_zx1[d][0][0] : &g_zx0[d][0][0];
        float*       hgl = layer ? &g_h1[d][0][0]  : &g_h0[d][0][0];
        unsigned* cnt    = &g_csync[eng];
        unsigned* cntzxd = &g_cntzx[d];

        // gate warp: remote hbuf addresses; lane r (r<8) owns flag delivery to rank r
        unsigned rs[2][8];
        unsigned rflag = 0;
        if (tid < 32) {
            #pragma unroll
            for (int b = 0; b < 2; b++) {
                unsigned a = smem_u32(&hbuf[b][c * 32 + tid]);
                #pragma unroll
                for (int r = 0; r < 8; r++) rs[b][r] = mapa_rank(a, (unsigned)r);
            }
            if (tid < 8) rflag = mapa_rank(smem_u32(&flags[c]), (unsigned)tid);
        }
        const unsigned myflag = smem_u32(&flags[tid & 7]);

        // fetch warp (tid 32..63): preload zbuf[0] = zx[step 0]
        if (tid >= 32 && tid < 64) {
            const int ft = tid - 32;
            if (layer == 1) {
                if (ft == 0) { while (acq_ld(cntzxd) < 16u) { } }
                __syncwarp();
            }
            #pragma unroll
            for (int gg = 0; gg < 4; gg++)
                zbuf[0][gg * 32 + ft] = __ldcg(zxs + 0 * 1024 + gg * 256 + c * 32 + ft);
        }
        __syncthreads();
        cluster_sync_asm();    // peers resident; hbuf[0] + flags initialized

        for (int s = 0; s < TT; s++) {
            const int sb = s & 1;
            if (s > 0) {
                // wait for all 8 producers to have pushed h[s-1] (flag >= s)
                if (tid < 8) {
                    while (ld_acq_sh(myflag) < (unsigned)s) { }
                }
                __syncthreads();
            }

            // dot over K half (f32x2 packed; h local via DSMEM push)
            unsigned long long acc0 = 0ull, acc1 = 0ull;
            const float* hv = &hbuf[sb][p * 128];
            #pragma unroll
            for (int i = 0; i < 128; i += 8) {
                float4 ha = *(const float4*)&hv[i];
                float4 hb = *(const float4*)&hv[i + 4];
                fma2(acc0, w2[i / 2],     pack2(ha.x, ha.y));
                fma2(acc1, w2[i / 2 + 1], pack2(ha.z, ha.w));
                fma2(acc0, w2[i / 2 + 2], pack2(hb.x, hb.y));
                fma2(acc1, w2[i / 2 + 3], pack2(hb.z, hb.w));
            }
            float2 a0 = unpack2(acc0), a1 = unpack2(acc1);
            redb[sb][p * 128 + l] = (a0.x + a0.y) + (a1.x + a1.y);
            __syncthreads();               // dot complete CTA-wide

            if (tid < 32) {
                // gate warp
                float z[4];
                #pragma unroll
                for (int gg = 0; gg < 4; gg++)
                    z[gg] = redb[sb][gg * 32 + tid] + redb[sb][128 + gg * 32 + tid]
                          + zbuf[sb][gg * 32 + tid];
                float cn = fsig(z[2] + 1.0f) * cs[tid] + fsig(z[0]) * ftanh(z[1]);
                float hn = fsig(z[3]) * ftanh(cn);
                cs[tid] = cn;

                // push h[s] into all 8 peers' other buffer (incl. self)
                const int wb = (s + 1) & 1;
                #pragma unroll
                for (int r = 0; r < 8; r++) st_cluster_f32(rs[wb][r], hn);
                __syncwarp();
                // signal: ONE fence, then 8 plain flag stores in parallel
                if (tid < 8) {
                    fence_acqrel_cluster();
                    st_cluster_u32(rflag, (unsigned)(s + 1));
                }
                // publish to L2 (helpers for L0; phaseC for L1) — off critical path
                __stcg(hgl + (size_t)s * HD + c * 32 + tid, hn);
                __syncwarp();
                if (tid == 0 && layer == 0) rel_add(cnt);
            } else if (tid < 64) {
                // fetch warp: prefetch zx for step s+1
                if (s + 1 < TT) {
                    const int ft = tid - 32;
                    if (layer == 1) {
                        if (ft == 0) {
                            unsigned tgt = 16u * (unsigned)(s + 2);
                            while (acq_ld(cntzxd) < tgt) { }
                        }
                        __syncwarp();
                    }
                    #pragma unroll
                    for (int gg = 0; gg < 4; gg++)
                        zbuf[(s + 1) & 1][gg * 32 + ft] =
                            __ldcg(zxs + (size_t)(s + 1) * 1024 + gg * 256 + c * 32 + ft);
                }
            }
        }
        cluster_sync_asm();    // keep SMEM alive for in-flight peer stores
    } else {
        // ======================= helper CTAs (proven sync) ==================
        const int hix = bid - 32;
        const int d   = hix >> 4;
        const int hc  = hix & 15;
        const float* __restrict__ W    = d ? Wb1 : Wf1;
        const float* __restrict__ bias = d ? bb1 : bf1;
        const int p = tid >> 6;            // K quarter (64 rows of W1[0:256])
        const int l = tid & 63;            // col (64 per CTA)
        const int col = hc * 64 + l;

        float w[64];
        #pragma unroll
        for (int i = 0; i < 64; i++)
            w[i] = W[(size_t)(p * 64 + i) * 1024 + col];
        const float bb = (tid < 64) ? bias[hc * 64 + tid] : 0.0f;

        float* hs  = &hbuf[0][0];          // reuse engine smem
        float* red = &redb[0][0];
        unsigned* cnt0d  = &g_csync[d];    // L0 engine counter for this dir
        unsigned* cntzxd = &g_cntzx[d];
        const int koff = p * 64;

        for (int s = 0; s < TT; s++) {
            if (tid == 0) {
                unsigned tgt = 8u * (unsigned)(s + 1);   // 8 L0 CTAs per dir
                while (acq_ld(cnt0d) < tgt) { }
            }
            __syncthreads();
            hs[tid] = __ldcg(&g_h0[d][s][tid]);
            __syncthreads();

            float acc = 0.0f;
            #pragma unroll
            for (int i = 0; i < 64; i += 4) {
                float4 h4 = *(const float4*)&hs[koff + i];
                acc += w[i] * h4.x; acc += w[i + 1] * h4.y;
                acc += w[i + 2] * h4.z; acc += w[i + 3] * h4.w;
            }
            red[tid] = acc;
            __syncthreads();
            if (tid < 64) {
                float z = bb + red[tid] + red[64 + tid] + red[128 + tid] + red[192 + tid];
                __stcg(&g_zx1[d][s][hc * 64 + tid], z);
            }
            __syncthreads();               // all 64 stores issued before signal
            if (tid == 0) rel_add(cntzxd);
        }
    }
}

// ---------------- Phase C: final dense ---------------------------------------
__global__ void phaseC(const float* __restrict__ Wd, const float* __restrict__ bd,
                       float* __restrict__ out)
{
    const int chunk = blockIdx.x;
    const int o = threadIdx.x;
    __shared__ float hsm[8][512];
    for (int i = threadIdx.x; i < 8 * 512; i += 128) {
        int t8 = i >> 9, k = i & 511;
        int t = chunk * 8 + t8;
        hsm[t8][k] = (k < 256) ? g_h1[0][t][k] : g_h1[1][TT - 1 - t][k - 256];
    }
    __syncthreads();
    float b = bd[o];
    float acc[8];
    #pragma unroll
    for (int t8 = 0; t8 < 8; t8++) acc[t8] = b;
    #pragma unroll 8
    for (int k = 0; k < 512; k++) {
        float w = Wd[k * 128 + o];
        #pragma unroll
        for (int t8 = 0; t8 < 8; t8++) acc[t8] += hsm[t8][k] * w;
    }
    #pragma unroll
    for (int t8 = 0; t8 < 8; t8++) out[(chunk * 8 + t8) * 128 + o] = acc[t8];
}

// ---------------- launch -----------------------------------------------------
extern "C" void kernel_launch(void* const* d_in, const int* in_sizes, int n_in,
                              void* d_out, int out_size)
{
    (void)in_sizes; (void)n_in; (void)out_size;
    const float* x        = (const float*)d_in[0];
    const float* fw_state = (const float*)d_in[1];
    const float* bw_state = (const float*)d_in[2];
    const float* Wf0 = (const float*)d_in[3];
    const float* bf0 = (const float*)d_in[4];
    const float* Wf1 = (const float*)d_in[5];
    const float* bf1 = (const float*)d_in[6];
    const float* Wb0 = (const float*)d_in[7];
    const float* bb0 = (const float*)d_in[8];
    const float* Wb1 = (const float*)d_in[9];
    const float* bb1 = (const float*)d_in[10];
    const float* Wd  = (const float*)d_in[11];
    const float* bd  = (const float*)d_in[12];

    phaseA<<<256, 256>>>(x, Wf0, bf0, Wb0, bb0);

    cudaLaunchConfig_t cfg = {};
    cfg.gridDim  = dim3(64, 1, 1);
    cfg.blockDim = dim3(256, 1, 1);
    cfg.dynamicSmemBytes = 0;
    cfg.stream = 0;
    cudaLaunchAttribute attr[1];
    attr[0].id = cudaLaunchAttributeClusterDimension;
    attr[0].val.clusterDim.x = 8;
    attr[0].val.clusterDim.y = 1;
    attr[0].val.clusterDim.z = 1;
    cfg.attrs = attr;
    cfg.numAttrs = 1;
    cudaLaunchKernelEx(&cfg, phaseB, fw_state, bw_state,
                       Wf0, Wf1, bf1, Wb0, Wb1, bb1);

    phaseC<<<64, 128>>>(Wd, bd, (float*)d_out);
}

// round 11
// speedup vs baseline: 1.7814x; 1.0410x over previous
#include <cuda_runtime.h>
#include <cstddef>
#include <cstdint>

// Bidirectional 2-layer LSTM; only batch row 255 feeds the output (B -> 1).
// Round 11: R10 engines unchanged. Helper stage identified as the pipeline
// bottleneck (R7/R9/R10 engine variants all ~880us). Fix: 2x helpers with
// step-parity decomposition (even/odd groups), per-parity zx1 counters.

#define TT 512
#define HD 256
#define DD 128
#define BLAST 255

// ---------------- scratch (static device memory) ----------------------------
__device__ float g_zx0[2][TT][1024];   // layer0 x-part + bias (phaseA)
__device__ float g_zx1[2][TT][1024];   // layer1 x-part + bias (helpers)
__device__ float g_h0[2][TT][HD];      // layer0 h (published for helpers)
__device__ float g_h1[2][TT][HD];      // layer1 h (for phaseC)
__device__ unsigned g_csync[4];        // L0 step counters (helpers' feed)
__device__ unsigned g_cntzx[2][2];     // helper zx1 counters [dir][parity]

// fast saturating gate math (proven R5-R10)
__device__ __forceinline__ float fsig(float x) {
    return __fdividef(1.0f, 1.0f + __expf(-x));
}
__device__ __forceinline__ float ftanh(float x) {
    return 1.0f - __fdividef(2.0f, __expf(2.0f * x) + 1.0f);
}

// proven counter ops (R2/R5/R7-R10)
__device__ __forceinline__ void rel_add(unsigned* p) {
    asm volatile("red.release.gpu.global.add.u32 [%0], 1;" :: "l"(p) : "memory");
}
__device__ __forceinline__ unsigned acq_ld(const unsigned* p) {
    unsigned v;
    asm volatile("ld.acquire.gpu.global.u32 %0, [%1];" : "=r"(v) : "l"(p) : "memory");
    return v;
}

// cluster primitives (proven R6-R10)
__device__ __forceinline__ unsigned smem_u32(const void* p) {
    return (unsigned)__cvta_generic_to_shared(p);
}
__device__ __forceinline__ unsigned mapa_rank(unsigned a, unsigned r) {
    unsigned o; asm("mapa.shared::cluster.u32 %0,%1,%2;" : "=r"(o) : "r"(a), "r"(r));
    return o;
}
__device__ __forceinline__ void st_cluster_f32(unsigned a, float v) {
    asm volatile("st.shared::cluster.f32 [%0],%1;" :: "r"(a), "f"(v) : "memory");
}
__device__ __forceinline__ void st_cluster_u32(unsigned a, unsigned v) {
    asm volatile("st.shared::cluster.u32 [%0],%1;" :: "r"(a), "r"(v) : "memory");
}
__device__ __forceinline__ void fence_acqrel_cluster() {
    asm volatile("fence.acq_rel.cluster;" ::: "memory");
}
__device__ __forceinline__ unsigned ld_acq_sh(unsigned a) {
    unsigned v;
    asm volatile("ld.acquire.cluster.shared::cta.u32 %0,[%1];"
                 : "=r"(v) : "r"(a) : "memory");
    return v;
}
__device__ __forceinline__ void cluster_sync_asm() {
    asm volatile("barrier.cluster.arrive.aligned;" ::: "memory");
    asm volatile("barrier.cluster.wait.aligned;" ::: "memory");
}

// packed f32x2 helpers (proven R8/R10)
__device__ __forceinline__ unsigned long long pack2(float lo, float hi) {
    unsigned long long r; asm("mov.b64 %0,{%1,%2};" : "=l"(r) : "f"(lo), "f"(hi));
    return r;
}
__device__ __forceinline__ void fma2(unsigned long long& acc, unsigned long long a,
                                     unsigned long long b) {
    asm("fma.rn.f32x2 %0,%1,%2,%0;" : "+l"(acc) : "l"(a), "l"(b));
}
__device__ __forceinline__ float2 unpack2(unsigned long long v) {
    float2 f; asm("mov.b64 {%0,%1},%2;" : "=f"(f.x), "=f"(f.y) : "l"(v));
    return f;
}

// ---------------- Phase A (proven R5-R10) ------------------------------------
__global__ void phaseA(const float* __restrict__ x,
                       const float* __restrict__ Wf0, const float* __restrict__ bf0,
                       const float* __restrict__ Wb0, const float* __restrict__ bb0)
{
    if (blockIdx.x == 0 && threadIdx.x < 8) {
        if (threadIdx.x < 4) g_csync[threadIdx.x] = 0u;
        else ((unsigned*)g_cntzx)[threadIdx.x - 4] = 0u;
    }

    const int d     = blockIdx.x >> 7;
    const int chunk = blockIdx.x & 127;
    const float* __restrict__ W    = d ? Wb0 : Wf0;
    const float* __restrict__ bias = d ? bb0 : bf0;

    __shared__ float xs[4][DD];
    const int tid = threadIdx.x;
    for (int i = tid; i < 4 * DD; i += 256) {
        int t4 = i >> 7, k = i & 127;
        int s = chunk * 4 + t4;
        int t = d ? (TT - 1 - s) : s;
        xs[t4][k] = x[(size_t)BLAST * TT * DD + (size_t)t * DD + k];
    }
    __syncthreads();

    float acc[4][4];
    #pragma unroll
    for (int j = 0; j < 4; j++) {
        float b = bias[tid + j * 256];
        #pragma unroll
        for (int t4 = 0; t4 < 4; t4++) acc[j][t4] = b;
    }
    #pragma unroll 4
    for (int k = 0; k < DD; k++) {
        float xv[4];
        #pragma unroll
        for (int t4 = 0; t4 < 4; t4++) xv[t4] = xs[t4][k];
        #pragma unroll
        for (int j = 0; j < 4; j++) {
            float w = W[k * 1024 + tid + j * 256];
            #pragma unroll
            for (int t4 = 0; t4 < 4; t4++) acc[j][t4] += xv[t4] * w;
        }
    }
    #pragma unroll
    for (int j = 0; j < 4; j++)
        #pragma unroll
        for (int t4 = 0; t4 < 4; t4++)
            g_zx0[d][chunk * 4 + t4][tid + j * 256] = acc[j][t4];
}

// ---------------- Phase B ----------------------------------------------------
// grid 96 x 256 threads, cluster (8,1,1).
//   bid 0..31 : engines. eng = bid>>3 (0:L0fw 1:L0bw 2:L1fw 3:L1bw), c = bid&7.
//   bid 32..95: helpers. hix = bid-32: d = hix>>5, pg = (hix&31)>>4 (step parity),
//               hc = hix&15 (64-col block). Group pg handles steps s = 2k+pg.
__global__ void __launch_bounds__(256, 1) phaseB(
    const float* __restrict__ fw_state, const float* __restrict__ bw_state,
    const float* __restrict__ Wf0,
    const float* __restrict__ Wf1, const float* __restrict__ bf1,
    const float* __restrict__ Wb0,
    const float* __restrict__ Wb1, const float* __restrict__ bb1)
{
    __shared__ __align__(16) float hbuf[2][HD];   // h double buffer (DSMEM target)
    __shared__ float redb[2][HD];                 // partial sums (double buffer)
    __shared__ float zbuf[2][128];                // prefetched zx (double buffer)
    __shared__ float cs[32];
    __shared__ unsigned flags[8];                 // per-producer monotonic step flags

    const int bid = blockIdx.x;
    const int tid = threadIdx.x;

    if (bid < 32) {
        // ======================= cluster engine (R10, unchanged) ============
        const int eng = bid >> 3, c = bid & 7;
        const int layer = eng >> 1, d = eng & 1;
        const float* __restrict__ state = d ? bw_state : fw_state;
        const float* __restrict__ W = layer ? (d ? Wb1 : Wf1) : (d ? Wb0 : Wf0);
        const int rowbase = layer ? 256 : 128;   // recurrent rows of W

        const int p = tid >> 7;            // K half (128 rows)
        const int l = tid & 127;           // local col 0..127
        const int g = l >> 5, j = l & 31;
        const int gcol = g * 256 + c * 32 + j;

        unsigned long long w2[64];
        #pragma unroll
        for (int i = 0; i < 64; i++) {
            const float* wp = W + (size_t)(rowbase + p * 128 + 2 * i) * 1024 + gcol;
            w2[i] = pack2(wp[0], wp[1024]);
        }

        const float* srow = state + (size_t)BLAST * 1024 + layer * 512;
        hbuf[0][tid] = srow[256 + tid];    // h_init, consumed at step 0
        if (tid < 32) cs[tid] = srow[c * 32 + tid];
        if (tid < 8) flags[tid] = 0u;

        const float* zxs = layer ? &g_zx1[d][0][0] : &g_zx0[d][0][0];
        float*       hgl = layer ? &g_h1[d][0][0]  : &g_h0[d][0][0];
        unsigned* cnt    = &g_csync[eng];

        unsigned rs[2][8];
        unsigned rflag = 0;
        if (tid < 32) {
            #pragma unroll
            for (int b = 0; b < 2; b++) {
                unsigned a = smem_u32(&hbuf[b][c * 32 + tid]);
                #pragma unroll
                for (int r = 0; r < 8; r++) rs[b][r] = mapa_rank(a, (unsigned)r);
            }
            if (tid < 8) rflag = mapa_rank(smem_u32(&flags[c]), (unsigned)tid);
        }
        const unsigned myflag = smem_u32(&flags[tid & 7]);

        // fetch warp (tid 32..63): preload zbuf[0] = zx[step 0]
        if (tid >= 32 && tid < 64) {
            const int ft = tid - 32;
            if (layer == 1) {
                if (ft == 0) { while (acq_ld(&g_cntzx[d][0]) < 16u) { } }
                __syncwarp();
            }
            #pragma unroll
            for (int gg = 0; gg < 4; gg++)
                zbuf[0][gg * 32 + ft] = __ldcg(zxs + 0 * 1024 + gg * 256 + c * 32 + ft);
        }
        __syncthreads();
        cluster_sync_asm();    // peers resident; hbuf[0] + flags initialized

        for (int s = 0; s < TT; s++) {
            const int sb = s & 1;
            if (s > 0) {
                if (tid < 8) {
                    while (ld_acq_sh(myflag) < (unsigned)s) { }
                }
                __syncthreads();
            }

            // dot over K half (f32x2 packed; h local via DSMEM push)
            unsigned long long acc0 = 0ull, acc1 = 0ull;
            const float* hv = &hbuf[sb][p * 128];
            #pragma unroll
            for (int i = 0; i < 128; i += 8) {
                float4 ha = *(const float4*)&hv[i];
                float4 hb = *(const float4*)&hv[i + 4];
                fma2(acc0, w2[i / 2],     pack2(ha.x, ha.y));
                fma2(acc1, w2[i / 2 + 1], pack2(ha.z, ha.w));
                fma2(acc0, w2[i / 2 + 2], pack2(hb.x, hb.y));
                fma2(acc1, w2[i / 2 + 3], pack2(hb.z, hb.w));
            }
            float2 a0 = unpack2(acc0), a1 = unpack2(acc1);
            redb[sb][p * 128 + l] = (a0.x + a0.y) + (a1.x + a1.y);
            __syncthreads();               // dot complete CTA-wide

            if (tid < 32) {
                float z[4];
                #pragma unroll
                for (int gg = 0; gg < 4; gg++)
                    z[gg] = redb[sb][gg * 32 + tid] + redb[sb][128 + gg * 32 + tid]
                          + zbuf[sb][gg * 32 + tid];
                float cn = fsig(z[2] + 1.0f) * cs[tid] + fsig(z[0]) * ftanh(z[1]);
                float hn = fsig(z[3]) * ftanh(cn);
                cs[tid] = cn;

                const int wb = (s + 1) & 1;
                #pragma unroll
                for (int r = 0; r < 8; r++) st_cluster_f32(rs[wb][r], hn);
                __syncwarp();
                if (tid < 8) {
                    fence_acqrel_cluster();
                    st_cluster_u32(rflag, (unsigned)(s + 1));
                }
                __stcg(hgl + (size_t)s * HD + c * 32 + tid, hn);
                __syncwarp();
                if (tid == 0 && layer == 0) rel_add(cnt);
            } else if (tid < 64) {
                // fetch warp: prefetch zx for step u = s+1
                if (s + 1 < TT) {
                    const int u = s + 1;
                    const int ft = tid - 32;
                    if (layer == 1) {
                        if (ft == 0) {
                            unsigned tgt = 16u * (unsigned)((u >> 1) + 1);
                            while (acq_ld(&g_cntzx[d][u & 1]) < tgt) { }
                        }
                        __syncwarp();
                    }
                    #pragma unroll
                    for (int gg = 0; gg < 4; gg++)
                        zbuf[u & 1][gg * 32 + ft] =
                            __ldcg(zxs + (size_t)u * 1024 + gg * 256 + c * 32 + ft);
                }
            }
        }
        cluster_sync_asm();    // keep SMEM alive for in-flight peer stores
    } else {
        // ===== helper CTAs: zx1 = h0 @ W1[0:256] + b1, parity-decomposed ====
        const int hix = bid - 32;          // 0..63
        const int d   = hix >> 5;          // direction
        const int pg  = (hix & 31) >> 4;   // step parity group (0=even,1=odd)
        const int hc  = hix & 15;          // 64-col block
        const float* __restrict__ W    = d ? Wb1 : Wf1;
        const float* __restrict__ bias = d ? bb1 : bf1;
        const int p = tid >> 6;            // K quarter (64 rows of W1[0:256])
        const int l = tid & 63;            // col (64 per CTA)
        const int col = hc * 64 + l;

        float w[64];
        #pragma unroll
        for (int i = 0; i < 64; i++)
            w[i] = W[(size_t)(p * 64 + i) * 1024 + col];
        const float bb = (tid < 64) ? bias[hc * 64 + tid] : 0.0f;

        float* hs  = &hbuf[0][0];          // reuse engine smem
        float* red = &redb[0][0];
        unsigned* cnt0d  = &g_csync[d];    // L0 engine counter for this dir
        unsigned* cntzxd = &g_cntzx[d][pg];
        const int koff = p * 64;

        for (int k = 0; k < TT / 2; k++) {
            const int s = 2 * k + pg;
            if (tid == 0) {
                unsigned tgt = 8u * (unsigned)(s + 1);   // 8 L0 CTAs per dir
                while (acq_ld(cnt0d) < tgt) { }
            }
            __syncthreads();
            hs[tid] = __ldcg(&g_h0[d][s][tid]);
            __syncthreads();

            float acc = 0.0f;
            #pragma unroll
            for (int i = 0; i < 64; i += 4) {
                float4 h4 = *(const float4*)&hs[koff + i];
                acc += w[i] * h4.x; acc += w[i + 1] * h4.y;
                acc += w[i + 2] * h4.z; acc += w[i + 3] * h4.w;
            }
            red[tid] = acc;
            __syncthreads();
            if (tid < 64) {
                float z = bb + red[tid] + red[64 + tid] + red[128 + tid] + red[192 + tid];
                __stcg(&g_zx1[d][s][hc * 64 + tid], z);
            }
            __syncthreads();               // all 64 stores issued before signal
            if (tid == 0) rel_add(cntzxd); // counter hits 16*(k+1) per (d,pg)
        }
    }
}

// ---------------- Phase C: final dense ---------------------------------------
__global__ void phaseC(const float* __restrict__ Wd, const float* __restrict__ bd,
                       float* __restrict__ out)
{
    const int chunk = blockIdx.x;
    const int o = threadIdx.x;
    __shared__ float hsm[8][512];
    for (int i = threadIdx.x; i < 8 * 512; i += 128) {
        int t8 = i >> 9, k = i & 511;
        int t = chunk * 8 + t8;
        hsm[t8][k] = (k < 256) ? g_h1[0][t][k] : g_h1[1][TT - 1 - t][k - 256];
    }
    __syncthreads();
    float b = bd[o];
    float acc[8];
    #pragma unroll
    for (int t8 = 0; t8 < 8; t8++) acc[t8] = b;
    #pragma unroll 8
    for (int k = 0; k < 512; k++) {
        float w = Wd[k * 128 + o];
        #pragma unroll
        for (int t8 = 0; t8 < 8; t8++) acc[t8] += hsm[t8][k] * w;
    }
    #pragma unroll
    for (int t8 = 0; t8 < 8; t8++) out[(chunk * 8 + t8) * 128 + o] = acc[t8];
}

// ---------------- launch -----------------------------------------------------
extern "C" void kernel_launch(void* const* d_in, const int* in_sizes, int n_in,
                              void* d_out, int out_size)
{
    (void)in_sizes; (void)n_in; (void)out_size;
    const float* x        = (const float*)d_in[0];
    const float* fw_state = (const float*)d_in[1];
    const float* bw_state = (const float*)d_in[2];
    const float* Wf0 = (const float*)d_in[3];
    const float* bf0 = (const float*)d_in[4];
    const float* Wf1 = (const float*)d_in[5];
    const float* bf1 = (const float*)d_in[6];
    const float* Wb0 = (const float*)d_in[7];
    const float* bb0 = (const float*)d_in[8];
    const float* Wb1 = (const float*)d_in[9];
    const float* bb1 = (const float*)d_in[10];
    const float* Wd  = (const float*)d_in[11];
    const float* bd  = (const float*)d_in[12];

    phaseA<<<256, 256>>>(x, Wf0, bf0, Wb0, bb0);

    cudaLaunchConfig_t cfg = {};
    cfg.gridDim  = dim3(96, 1, 1);
    cfg.blockDim = dim3(256, 1, 1);
    cfg.dynamicSmemBytes = 0;
    cfg.stream = 0;
    cudaLaunchAttribute attr[1];
    attr[0].id = cudaLaunchAttributeClusterDimension;
    attr[0].val.clusterDim.x = 8;
    attr[0].val.clusterDim.y = 1;
    attr[0].val.clusterDim.z = 1;
    cfg.attrs = attr;
    cfg.numAttrs = 1;
    cudaLaunchKernelEx(&cfg, phaseB, fw_state, bw_state,
                       Wf0, Wf1, bf1, Wb0, Wb1, bb1);

    phaseC<<<64, 128>>>(Wd, bd, (float*)d_out);
}

// round 13
// speedup vs baseline: 2.0792x; 1.1672x over previous
#include <cuda_runtime.h>
#include <cstddef>
#include <cstdint>

// Bidirectional 2-layer LSTM; only batch row 255 feeds the output (B -> 1).
// Round 13 = Round 12 resubmitted unchanged (R12 bench was an infra failure:
// "GB300 container failed twice" — no measurement happened).
// R12 delta vs R11: L2 publish (stcg + gpu-scope release add) MOVED OFF the
// gate warp's critical path into the fetch warp, and the per-step wait
// flattened to an all-thread SMEM flag poll (no top __syncthreads).

#define TT 512
#define HD 256
#define DD 128
#define BLAST 255

// ---------------- scratch (static device memory) ----------------------------
__device__ float g_zx0[2][TT][1024];   // layer0 x-part + bias (phaseA)
__device__ float g_zx1[2][TT][1024];   // layer1 x-part + bias (helpers)
__device__ float g_h0[2][TT][HD];      // layer0 h (published for helpers)
__device__ float g_h1[2][TT][HD];      // layer1 h (for phaseC)
__device__ unsigned g_csync[4];        // L0 step counters (helpers' feed)
__device__ unsigned g_cntzx[2][2];     // helper zx1 counters [dir][parity]

// fast saturating gate math (proven R5-R11)
__device__ __forceinline__ float fsig(float x) {
    return __fdividef(1.0f, 1.0f + __expf(-x));
}
__device__ __forceinline__ float ftanh(float x) {
    return 1.0f - __fdividef(2.0f, __expf(2.0f * x) + 1.0f);
}

// proven counter ops (R2/R5/R7-R11)
__device__ __forceinline__ void rel_add(unsigned* p) {
    asm volatile("red.release.gpu.global.add.u32 [%0], 1;" :: "l"(p) : "memory");
}
__device__ __forceinline__ unsigned acq_ld(const unsigned* p) {
    unsigned v;
    asm volatile("ld.acquire.gpu.global.u32 %0, [%1];" : "=r"(v) : "l"(p) : "memory");
    return v;
}

// cluster primitives (proven R6-R11)
__device__ __forceinline__ unsigned smem_u32(const void* p) {
    return (unsigned)__cvta_generic_to_shared(p);
}
__device__ __forceinline__ unsigned mapa_rank(unsigned a, unsigned r) {
    unsigned o; asm("mapa.shared::cluster.u32 %0,%1,%2;" : "=r"(o) : "r"(a), "r"(r));
    return o;
}
__device__ __forceinline__ void st_cluster_f32(unsigned a, float v) {
    asm volatile("st.shared::cluster.f32 [%0],%1;" :: "r"(a), "f"(v) : "memory");
}
__device__ __forceinline__ void st_cluster_u32(unsigned a, unsigned v) {
    asm volatile("st.shared::cluster.u32 [%0],%1;" :: "r"(a), "r"(v) : "memory");
}
__device__ __forceinline__ void fence_acqrel_cluster() {
    asm volatile("fence.acq_rel.cluster;" ::: "memory");
}
__device__ __forceinline__ unsigned ld_acq_sh(unsigned a) {
    unsigned v;
    asm volatile("ld.acquire.cluster.shared::cta.u32 %0,[%1];"
                 : "=r"(v) : "r"(a) : "memory");
    return v;
}
__device__ __forceinline__ void cluster_sync_asm() {
    asm volatile("barrier.cluster.arrive.aligned;" ::: "memory");
    asm volatile("barrier.cluster.wait.aligned;" ::: "memory");
}

// packed f32x2 helpers (proven R8/R10/R11)
__device__ __forceinline__ unsigned long long pack2(float lo, float hi) {
    unsigned long long r; asm("mov.b64 %0,{%1,%2};" : "=l"(r) : "f"(lo), "f"(hi));
    return r;
}
__device__ __forceinline__ void fma2(unsigned long long& acc, unsigned long long a,
                                     unsigned long long b) {
    asm("fma.rn.f32x2 %0,%1,%2,%0;" : "+l"(acc) : "l"(a), "l"(b));
}
__device__ __forceinline__ float2 unpack2(unsigned long long v) {
    float2 f; asm("mov.b64 {%0,%1},%2;" : "=f"(f.x), "=f"(f.y) : "l"(v));
    return f;
}

// ---------------- Phase A (proven R5-R11) ------------------------------------
__global__ void phaseA(const float* __restrict__ x,
                       const float* __restrict__ Wf0, const float* __restrict__ bf0,
                       const float* __restrict__ Wb0, const float* __restrict__ bb0)
{
    if (blockIdx.x == 0 && threadIdx.x < 8) {
        if (threadIdx.x < 4) g_csync[threadIdx.x] = 0u;
        else ((unsigned*)g_cntzx)[threadIdx.x - 4] = 0u;
    }

    const int d     = blockIdx.x >> 7;
    const int chunk = blockIdx.x & 127;
    const float* __restrict__ W    = d ? Wb0 : Wf0;
    const float* __restrict__ bias = d ? bb0 : bf0;

    __shared__ float xs[4][DD];
    const int tid = threadIdx.x;
    for (int i = tid; i < 4 * DD; i += 256) {
        int t4 = i >> 7, k = i & 127;
        int s = chunk * 4 + t4;
        int t = d ? (TT - 1 - s) : s;
        xs[t4][k] = x[(size_t)BLAST * TT * DD + (size_t)t * DD + k];
    }
    __syncthreads();

    float acc[4][4];
    #pragma unroll
    for (int j = 0; j < 4; j++) {
        float b = bias[tid + j * 256];
        #pragma unroll
        for (int t4 = 0; t4 < 4; t4++) acc[j][t4] = b;
    }
    #pragma unroll 4
    for (int k = 0; k < DD; k++) {
        float xv[4];
        #pragma unroll
        for (int t4 = 0; t4 < 4; t4++) xv[t4] = xs[t4][k];
        #pragma unroll
        for (int j = 0; j < 4; j++) {
            float w = W[k * 1024 + tid + j * 256];
            #pragma unroll
            for (int t4 = 0; t4 < 4; t4++) acc[j][t4] += xv[t4] * w;
        }
    }
    #pragma unroll
    for (int j = 0; j < 4; j++)
        #pragma unroll
        for (int t4 = 0; t4 < 4; t4++)
            g_zx0[d][chunk * 4 + t4][tid + j * 256] = acc[j][t4];
}

// ---------------- Phase B ----------------------------------------------------
// grid 96 x 256 threads, cluster (8,1,1).
//   bid 0..31 : engines. eng = bid>>3 (0:L0fw 1:L0bw 2:L1fw 3:L1bw), c = bid&7.
//   bid 32..95: helpers. hix = bid-32: d = hix>>5, pg = (hix&31)>>4 (step parity),
//               hc = hix&15 (64-col block).
__global__ void __launch_bounds__(256, 1) phaseB(
    const float* __restrict__ fw_state, const float* __restrict__ bw_state,
    const float* __restrict__ Wf0,
    const float* __restrict__ Wf1, const float* __restrict__ bf1,
    const float* __restrict__ Wb0,
    const float* __restrict__ Wb1, const float* __restrict__ bb1)
{
    __shared__ __align__(16) float hbuf[2][HD];   // h double buffer (DSMEM target)
    __shared__ float redb[2][HD];                 // partial sums (double buffer)
    __shared__ float zbuf[2][128];                // prefetched zx (double buffer)
    __shared__ float cs[32];
    __shared__ unsigned flags[8];                 // per-producer monotonic step flags

    const int bid = blockIdx.x;
    const int tid = threadIdx.x;

    if (bid < 32) {
        // ======================= cluster engine =============================
        const int eng = bid >> 3, c = bid & 7;
        const int layer = eng >> 1, d = eng & 1;
        const float* __restrict__ state = d ? bw_state : fw_state;
        const float* __restrict__ W = layer ? (d ? Wb1 : Wf1) : (d ? Wb0 : Wf0);
        const int rowbase = layer ? 256 : 128;   // recurrent rows of W

        const int p = tid >> 7;            // K half (128 rows)
        const int l = tid & 127;           // local col 0..127
        const int g = l >> 5, j = l & 31;
        const int gcol = g * 256 + c * 32 + j;

        unsigned long long w2[64];
        #pragma unroll
        for (int i = 0; i < 64; i++) {
            const float* wp = W + (size_t)(rowbase + p * 128 + 2 * i) * 1024 + gcol;
            w2[i] = pack2(wp[0], wp[1024]);
        }

        const float* srow = state + (size_t)BLAST * 1024 + layer * 512;
        hbuf[0][tid] = srow[256 + tid];    // h_init, consumed at step 0
        if (tid < 32) cs[tid] = srow[c * 32 + tid];
        if (tid < 8) flags[tid] = 0u;

        const float* zxs = layer ? &g_zx1[d][0][0] : &g_zx0[d][0][0];
        float*       hgl = layer ? &g_h1[d][0][0]  : &g_h0[d][0][0];
        unsigned* cnt    = &g_csync[eng];

        unsigned rs[2][8];
        unsigned rflag = 0;
        if (tid < 32) {
            #pragma unroll
            for (int b = 0; b < 2; b++) {
                unsigned a = smem_u32(&hbuf[b][c * 32 + tid]);
                #pragma unroll
                for (int r = 0; r < 8; r++) rs[b][r] = mapa_rank(a, (unsigned)r);
            }
            if (tid < 8) rflag = mapa_rank(smem_u32(&flags[c]), (unsigned)tid);
        }
        const unsigned myflag = smem_u32(&flags[tid & 7]);

        // fetch warp (tid 32..63): preload zbuf[0] = zx[step 0]
        if (tid >= 32 && tid < 64) {
            const int ft = tid - 32;
            if (layer == 1) {
                if (ft == 0) { while (acq_ld(&g_cntzx[d][0]) < 16u) { } }
                __syncwarp();
            }
            #pragma unroll
            for (int gg = 0; gg < 4; gg++)
                zbuf[0][gg * 32 + ft] = __ldcg(zxs + 0 * 1024 + gg * 256 + c * 32 + ft);
        }
        __syncthreads();
        cluster_sync_asm();    // peers resident; hbuf[0] + flags initialized

        for (int s = 0; s < TT; s++) {
            const int sb = s & 1;
            // all threads poll their own flag word (no top __syncthreads):
            // flag >= s means all 8 producers' h[s-1] pushes have landed.
            if (s > 0) {
                while (ld_acq_sh(myflag) < (unsigned)s) { }
            }

            // dot over K half (f32x2 packed; h local via DSMEM push)
            unsigned long long acc0 = 0ull, acc1 = 0ull;
            const float* hv = &hbuf[sb][p * 128];
            #pragma unroll
            for (int i = 0; i < 128; i += 8) {
                float4 ha = *(const float4*)&hv[i];
                float4 hb = *(const float4*)&hv[i + 4];
                fma2(acc0, w2[i / 2],     pack2(ha.x, ha.y));
                fma2(acc1, w2[i / 2 + 1], pack2(ha.z, ha.w));
                fma2(acc0, w2[i / 2 + 2], pack2(hb.x, hb.y));
                fma2(acc1, w2[i / 2 + 3], pack2(hb.z, hb.w));
            }
            float2 a0 = unpack2(acc0), a1 = unpack2(acc1);
            redb[sb][p * 128 + l] = (a0.x + a0.y) + (a1.x + a1.y);
            __syncthreads();               // dot complete CTA-wide

            if (tid < 32) {
                // gate warp: pure recurrence work, NO L2 traffic
                float z[4];
                #pragma unroll
                for (int gg = 0; gg < 4; gg++)
                    z[gg] = redb[sb][gg * 32 + tid] + redb[sb][128 + gg * 32 + tid]
                          + zbuf[sb][gg * 32 + tid];
                float cn = fsig(z[2] + 1.0f) * cs[tid] + fsig(z[0]) * ftanh(z[1]);
                float hn = fsig(z[3]) * ftanh(cn);
                cs[tid] = cn;

                const int wb = (s + 1) & 1;
                #pragma unroll
                for (int r = 0; r < 8; r++) st_cluster_f32(rs[wb][r], hn);
                __syncwarp();
                if (tid < 8) {
                    fence_acqrel_cluster();
                    st_cluster_u32(rflag, (unsigned)(s + 1));
                }
            } else if (tid < 64) {
                const int ft = tid - 32;
                // publish h[s-1] to L2 + helper signal — OFF the critical path
                // (hbuf[sb] = h[s-1] proven complete by this thread's flag wait)
                if (s > 0) {
                    __stcg(hgl + (size_t)(s - 1) * HD + c * 32 + ft,
                           hbuf[sb][c * 32 + ft]);
                    __syncwarp();
                    if (ft == 0 && layer == 0) rel_add(cnt);
                }
                // prefetch zbuf for step u = s+1
                if (s + 1 < TT) {
                    const int u = s + 1;
                    if (layer == 1) {
                        if (ft == 0) {
                            unsigned tgt = 16u * (unsigned)((u >> 1) + 1);
                            while (acq_ld(&g_cntzx[d][u & 1]) < tgt) { }
                        }
                        __syncwarp();
                    }
                    #pragma unroll
                    for (int gg = 0; gg < 4; gg++)
                        zbuf[u & 1][gg * 32 + ft] =
                            __ldcg(zxs + (size_t)u * 1024 + gg * 256 + c * 32 + ft);
                }
            }
        }
        // post-loop: fetch warp publishes the final h[TT-1]
        if (tid >= 32 && tid < 64) {
            const int ft = tid - 32;
            while (ld_acq_sh(myflag) < (unsigned)TT) { }
            __stcg(hgl + (size_t)(TT - 1) * HD + c * 32 + ft,
                   hbuf[TT & 1][c * 32 + ft]);
            __syncwarp();
            if (ft == 0 && layer == 0) rel_add(cnt);
        }
        cluster_sync_asm();    // keep SMEM alive for in-flight peer stores
    } else {
        // ===== helper CTAs: zx1 = h0 @ W1[0:256] + b1, parity-decomposed ====
        const int hix = bid - 32;          // 0..63
        const int d   = hix >> 5;          // direction
        const int pg  = (hix & 31) >> 4;   // step parity group (0=even,1=odd)
        const int hc  = hix & 15;          // 64-col block
        const float* __restrict__ W    = d ? Wb1 : Wf1;
        const float* __restrict__ bias = d ? bb1 : bf1;
        const int p = tid >> 6;            // K quarter (64 rows of W1[0:256])
        const int l = tid & 63;            // col (64 per CTA)
        const int col = hc * 64 + l;

        float w[64];
        #pragma unroll
        for (int i = 0; i < 64; i++)
            w[i] = W[(size_t)(p * 64 + i) * 1024 + col];
        const float bb = (tid < 64) ? bias[hc * 64 + tid] : 0.0f;

        float* hs  = &hbuf[0][0];          // reuse engine smem
        float* red = &redb[0][0];
        unsigned* cnt0d  = &g_csync[d];    // L0 engine counter for this dir
        unsigned* cntzxd = &g_cntzx[d][pg];
        const int koff = p * 64;

        for (int k = 0; k < TT / 2; k++) {
            const int s = 2 * k + pg;
            if (tid == 0) {
                unsigned tgt = 8u * (unsigned)(s + 1);   // 8 L0 CTAs per dir
                while (acq_ld(cnt0d) < tgt) { }
            }
            __syncthreads();
            hs[tid] = __ldcg(&g_h0[d][s][tid]);
            __syncthreads();

            float acc = 0.0f;
            #pragma unroll
            for (int i = 0; i < 64; i += 4) {
                float4 h4 = *(const float4*)&hs[koff + i];
                acc += w[i] * h4.x; acc += w[i + 1] * h4.y;
                acc += w[i + 2] * h4.z; acc += w[i + 3] * h4.w;
            }
            red[tid] = acc;
            __syncthreads();
            if (tid < 64) {
                float z = bb + red[tid] + red[64 + tid] + red[128 + tid] + red[192 + tid];
                __stcg(&g_zx1[d][s][hc * 64 + tid], z);
            }
            __syncthreads();               // all 64 stores issued before signal
            if (tid == 0) rel_add(cntzxd); // counter hits 16*(k+1) per (d,pg)
        }
    }
}

// ---------------- Phase C: final dense ---------------------------------------
__global__ void phaseC(const float* __restrict__ Wd, const float* __restrict__ bd,
                       float* __restrict__ out)
{
    const int chunk = blockIdx.x;
    const int o = threadIdx.x;
    __shared__ float hsm[8][512];
    for (int i = threadIdx.x; i < 8 * 512; i += 128) {
        int t8 = i >> 9, k = i & 511;
        int t = chunk * 8 + t8;
        hsm[t8][k] = (k < 256) ? g_h1[0][t][k] : g_h1[1][TT - 1 - t][k - 256];
    }
    __syncthreads();
    float b = bd[o];
    float acc[8];
    #pragma unroll
    for (int t8 = 0; t8 < 8; t8++) acc[t8] = b;
    #pragma unroll 8
    for (int k = 0; k < 512; k++) {
        float w = Wd[k * 128 + o];
        #pragma unroll
        for (int t8 = 0; t8 < 8; t8++) acc[t8] += hsm[t8][k] * w;
    }
    #pragma unroll
    for (int t8 = 0; t8 < 8; t8++) out[(chunk * 8 + t8) * 128 + o] = acc[t8];
}

// ---------------- launch -----------------------------------------------------
extern "C" void kernel_launch(void* const* d_in, const int* in_sizes, int n_in,
                              void* d_out, int out_size)
{
    (void)in_sizes; (void)n_in; (void)out_size;
    const float* x        = (const float*)d_in[0];
    const float* fw_state = (const float*)d_in[1];
    const float* bw_state = (const float*)d_in[2];
    const float* Wf0 = (const float*)d_in[3];
    const float* bf0 = (const float*)d_in[4];
    const float* Wf1 = (const float*)d_in[5];
    const float* bf1 = (const float*)d_in[6];
    const float* Wb0 = (const float*)d_in[7];
    const float* bb0 = (const float*)d_in[8];
    const float* Wb1 = (const float*)d_in[9];
    const float* bb1 = (const float*)d_in[10];
    const float* Wd  = (const float*)d_in[11];
    const float* bd  = (const float*)d_in[12];

    phaseA<<<256, 256>>>(x, Wf0, bf0, Wb0, bb0);

    cudaLaunchConfig_t cfg = {};
    cfg.gridDim  = dim3(96, 1, 1);
    cfg.blockDim = dim3(256, 1, 1);
    cfg.dynamicSmemBytes = 0;
    cfg.stream = 0;
    cudaLaunchAttribute attr[1];
    attr[0].id = cudaLaunchAttributeClusterDimension;
    attr[0].val.clusterDim.x = 8;
    attr[0].val.clusterDim.y = 1;
    attr[0].val.clusterDim.z = 1;
    cfg.attrs = attr;
    cfg.numAttrs = 1;
    cudaLaunchKernelEx(&cfg, phaseB, fw_state, bw_state,
                       Wf0, Wf1, bf1, Wb0, Wb1, bb1);

    phaseC<<<64, 128>>>(Wd, bd, (float*)d_out);
}

// round 15
// speedup vs baseline: 2.5382x; 1.2207x over previous
#include <cuda_runtime.h>
#include <cstddef>
#include <cstdint>

// Bidirectional 2-layer LSTM; only batch row 255 feeds the output (B -> 1).
// Round 15 = Round 14 with ONE token hardened: st.async payload type .b32
// (bit-cast) instead of .f32 — the only unproven syntax in R14, and the one
// plausible kernel-side cause of the container failure. Design unchanged:
// DSMEM handoff fused into st.async + mbarrier complete_tx (each h push
// carries its own completion; no fence, no flag store, no flag poll).

#define TT 512
#define HD 256
#define DD 128
#define BLAST 255

// ---------------- scratch (static device memory) ----------------------------
__device__ float g_zx0[2][TT][1024];   // layer0 x-part + bias (phaseA)
__device__ float g_zx1[2][TT][1024];   // layer1 x-part + bias (helpers)
__device__ float g_h0[2][TT][HD];      // layer0 h (published for helpers)
__device__ float g_h1[2][TT][HD];      // layer1 h (for phaseC)
__device__ unsigned g_csync[4];        // L0 step counters (helpers' feed)
__device__ unsigned g_cntzx[2][2];     // helper zx1 counters [dir][parity]

// fast saturating gate math (proven R5-R13)
__device__ __forceinline__ float fsig(float x) {
    return __fdividef(1.0f, 1.0f + __expf(-x));
}
__device__ __forceinline__ float ftanh(float x) {
    return 1.0f - __fdividef(2.0f, __expf(2.0f * x) + 1.0f);
}

// proven counter ops (R2/R5/R7-R13)
__device__ __forceinline__ void rel_add(unsigned* p) {
    asm volatile("red.release.gpu.global.add.u32 [%0], 1;" :: "l"(p) : "memory");
}
__device__ __forceinline__ unsigned acq_ld(const unsigned* p) {
    unsigned v;
    asm volatile("ld.acquire.gpu.global.u32 %0, [%1];" : "=r"(v) : "l"(p) : "memory");
    return v;
}

// cluster primitives (proven R6-R13)
__device__ __forceinline__ unsigned smem_u32(const void* p) {
    return (unsigned)__cvta_generic_to_shared(p);
}
__device__ __forceinline__ unsigned mapa_rank(unsigned a, unsigned r) {
    unsigned o; asm("mapa.shared::cluster.u32 %0,%1,%2;" : "=r"(o) : "r"(a), "r"(r));
    return o;
}
__device__ __forceinline__ void cluster_sync_asm() {
    asm volatile("barrier.cluster.arrive.aligned;" ::: "memory");
    asm volatile("barrier.cluster.wait.aligned;" ::: "memory");
}

// mbarrier primitives (wait macro proven correct in R6)
__device__ __forceinline__ void mbar_init(unsigned a, unsigned cnt) {
    asm volatile("mbarrier.init.shared.b64 [%0],%1;" :: "r"(a), "r"(cnt) : "memory");
}
__device__ __forceinline__ void mbar_expect_tx(unsigned a, unsigned bytes) {
    asm volatile("mbarrier.arrive.expect_tx.shared.b64 _, [%0], %1;"
                 :: "r"(a), "r"(bytes) : "memory");
}
__device__ __forceinline__ void mbar_wait_parity(unsigned a, unsigned ph) {
    asm volatile(
        "{\n\t.reg .pred P;\n"
        "LAB%=:\n\t"
        "mbarrier.try_wait.parity.acquire.cluster.shared::cta.b64 P, [%0], %1;\n\t"
        "@!P bra LAB%=;\n\t}"
        :: "r"(a), "r"(ph) : "memory");
}
// fused data+signal push: 4-byte store whose completion feeds the remote
// mbarrier. Payload as .b32 (bit-cast) — the canonical st.async type.
__device__ __forceinline__ void st_async_b32(unsigned a, unsigned v, unsigned mb) {
    asm volatile(
        "st.async.shared::cluster.mbarrier::complete_tx::bytes.b32 [%0],%1,[%2];"
        :: "r"(a), "r"(v), "r"(mb) : "memory");
}

// packed f32x2 helpers (proven R8/R10-R13)
__device__ __forceinline__ unsigned long long pack2(float lo, float hi) {
    unsigned long long r; asm("mov.b64 %0,{%1,%2};" : "=l"(r) : "f"(lo), "f"(hi));
    return r;
}
__device__ __forceinline__ void fma2(unsigned long long& acc, unsigned long long a,
                                     unsigned long long b) {
    asm("fma.rn.f32x2 %0,%1,%2,%0;" : "+l"(acc) : "l"(a), "l"(b));
}
__device__ __forceinline__ float2 unpack2(unsigned long long v) {
    float2 f; asm("mov.b64 {%0,%1},%2;" : "=f"(f.x), "=f"(f.y) : "l"(v));
    return f;
}

// ---------------- Phase A (proven R5-R13) ------------------------------------
__global__ void phaseA(const float* __restrict__ x,
                       const float* __restrict__ Wf0, const float* __restrict__ bf0,
                       const float* __restrict__ Wb0, const float* __restrict__ bb0)
{
    if (blockIdx.x == 0 && threadIdx.x < 8) {
        if (threadIdx.x < 4) g_csync[threadIdx.x] = 0u;
        else ((unsigned*)g_cntzx)[threadIdx.x - 4] = 0u;
    }

    const int d     = blockIdx.x >> 7;
    const int chunk = blockIdx.x & 127;
    const float* __restrict__ W    = d ? Wb0 : Wf0;
    const float* __restrict__ bias = d ? bb0 : bf0;

    __shared__ float xs[4][DD];
    const int tid = threadIdx.x;
    for (int i = tid; i < 4 * DD; i += 256) {
        int t4 = i >> 7, k = i & 127;
        int s = chunk * 4 + t4;
        int t = d ? (TT - 1 - s) : s;
        xs[t4][k] = x[(size_t)BLAST * TT * DD + (size_t)t * DD + k];
    }
    __syncthreads();

    float acc[4][4];
    #pragma unroll
    for (int j = 0; j < 4; j++) {
        float b = bias[tid + j * 256];
        #pragma unroll
        for (int t4 = 0; t4 < 4; t4++) acc[j][t4] = b;
    }
    #pragma unroll 4
    for (int k = 0; k < DD; k++) {
        float xv[4];
        #pragma unroll
        for (int t4 = 0; t4 < 4; t4++) xv[t4] = xs[t4][k];
        #pragma unroll
        for (int j = 0; j < 4; j++) {
            float w = W[k * 1024 + tid + j * 256];
            #pragma unroll
            for (int t4 = 0; t4 < 4; t4++) acc[j][t4] += xv[t4] * w;
        }
    }
    #pragma unroll
    for (int j = 0; j < 4; j++)
        #pragma unroll
        for (int t4 = 0; t4 < 4; t4++)
            g_zx0[d][chunk * 4 + t4][tid + j * 256] = acc[j][t4];
}

// ---------------- Phase B ----------------------------------------------------
// grid 96 x 256 threads, cluster (8,1,1).
//   bid 0..31 : engines. eng = bid>>3 (0:L0fw 1:L0bw 2:L1fw 3:L1bw), c = bid&7.
//   bid 32..95: helpers. hix = bid-32: d = hix>>5, pg = (hix&31)>>4 (step parity),
//               hc = hix&15 (64-col block).
__global__ void __launch_bounds__(256, 1) phaseB(
    const float* __restrict__ fw_state, const float* __restrict__ bw_state,
    const float* __restrict__ Wf0,
    const float* __restrict__ Wf1, const float* __restrict__ bf1,
    const float* __restrict__ Wb0,
    const float* __restrict__ Wb1, const float* __restrict__ bb1)
{
    __shared__ __align__(16) float hbuf[2][HD];   // h double buffer (st.async target)
    __shared__ float redb[2][HD];                 // partial sums (double buffer)
    __shared__ float zbuf[2][128];                // prefetched zx (double buffer)
    __shared__ float cs[32];
    __shared__ __align__(8) unsigned long long mbars[2];  // one mbarrier per h buffer

    const int bid = blockIdx.x;
    const int tid = threadIdx.x;

    if (bid < 32) {
        // ======================= cluster engine =============================
        const int eng = bid >> 3, c = bid & 7;
        const int layer = eng >> 1, d = eng & 1;
        const float* __restrict__ state = d ? bw_state : fw_state;
        const float* __restrict__ W = layer ? (d ? Wb1 : Wf1) : (d ? Wb0 : Wf0);
        const int rowbase = layer ? 256 : 128;   // recurrent rows of W

        const int p = tid >> 7;            // K half (128 rows)
        const int l = tid & 127;           // local col 0..127
        const int g = l >> 5, j = l & 31;
        const int gcol = g * 256 + c * 32 + j;

        unsigned long long w2[64];
        #pragma unroll
        for (int i = 0; i < 64; i++) {
            const float* wp = W + (size_t)(rowbase + p * 128 + 2 * i) * 1024 + gcol;
            w2[i] = pack2(wp[0], wp[1024]);
        }

        const float* srow = state + (size_t)BLAST * 1024 + layer * 512;
        hbuf[0][tid] = srow[256 + tid];    // h_init, consumed at step 0
        if (tid < 32) cs[tid] = srow[c * 32 + tid];
        if (tid == 0) {
            // one phase = 8 producers x 32 floats x 4B = 1024 bytes + 1 arrive
            mbar_init(smem_u32(&mbars[0]), 1u);
            mbar_init(smem_u32(&mbars[1]), 1u);
            mbar_expect_tx(smem_u32(&mbars[0]), 1024u);
            mbar_expect_tx(smem_u32(&mbars[1]), 1024u);
        }

        const float* zxs = layer ? &g_zx1[d][0][0] : &g_zx0[d][0][0];
        float*       hgl = layer ? &g_h1[d][0][0]  : &g_h0[d][0][0];
        unsigned* cnt    = &g_csync[eng];

        // gate warp: remote hbuf + remote mbarrier addresses (per buffer x rank)
        unsigned rs[2][8], rmb[2][8];
        if (tid < 32) {
            #pragma unroll
            for (int b = 0; b < 2; b++) {
                unsigned a = smem_u32(&hbuf[b][c * 32 + tid]);
                unsigned m = smem_u32(&mbars[b]);
                #pragma unroll
                for (int r = 0; r < 8; r++) {
                    rs[b][r]  = mapa_rank(a, (unsigned)r);
                    rmb[b][r] = mapa_rank(m, (unsigned)r);
                }
            }
        }
        const unsigned mloc[2] = { smem_u32(&mbars[0]), smem_u32(&mbars[1]) };
        unsigned ph[2] = { 0u, 0u };       // per-buffer phase parity

        // fetch warp (tid 32..63): preload zbuf[0] = zx[step 0]
        if (tid >= 32 && tid < 64) {
            const int ft = tid - 32;
            if (layer == 1) {
                if (ft == 0) { while (acq_ld(&g_cntzx[d][0]) < 16u) { } }
                __syncwarp();
            }
            #pragma unroll
            for (int gg = 0; gg < 4; gg++)
                zbuf[0][gg * 32 + ft] = __ldcg(zxs + 0 * 1024 + gg * 256 + c * 32 + ft);
        }
        __syncthreads();
        cluster_sync_asm();    // peers resident; hbuf[0] + mbarriers initialized

        for (int s = 0; s < TT; s++) {
            const int sb = s & 1;
            // wait: mbarrier flips when all 1024 bytes of h[s-1] have landed
            // (acquire makes the pushed data visible)
            if (s > 0) {
                mbar_wait_parity(mloc[sb], ph[sb]);
                ph[sb] ^= 1u;
                if (tid == 32)                       // re-arm for step s+2's use
                    mbar_expect_tx(mloc[sb], 1024u);
            }

            // dot over K half (f32x2 packed; h local via st.async push)
            unsigned long long acc0 = 0ull, acc1 = 0ull;
            const float* hv = &hbuf[sb][p * 128];
            #pragma unroll
            for (int i = 0; i < 128; i += 8) {
                float4 ha = *(const float4*)&hv[i];
                float4 hb = *(const float4*)&hv[i + 4];
                fma2(acc0, w2[i / 2],     pack2(ha.x, ha.y));
                fma2(acc1, w2[i / 2 + 1], pack2(ha.z, ha.w));
                fma2(acc0, w2[i / 2 + 2], pack2(hb.x, hb.y));
                fma2(acc1, w2[i / 2 + 3], pack2(hb.z, hb.w));
            }
            float2 a0 = unpack2(acc0), a1 = unpack2(acc1);
            redb[sb][p * 128 + l] = (a0.x + a0.y) + (a1.x + a1.y);
            __syncthreads();               // dot complete CTA-wide

            if (tid < 32) {
                // gate warp: pure recurrence work
                float z[4];
                #pragma unroll
                for (int gg = 0; gg < 4; gg++)
                    z[gg] = redb[sb][gg * 32 + tid] + redb[sb][128 + gg * 32 + tid]
                          + zbuf[sb][gg * 32 + tid];
                float cn = fsig(z[2] + 1.0f) * cs[tid] + fsig(z[0]) * ftanh(z[1]);
                float hn = fsig(z[3]) * ftanh(cn);
                cs[tid] = cn;

                // fused push: data + completion signal in one op per peer
                const int wb = (s + 1) & 1;
                const unsigned hb32 = __float_as_uint(hn);
                #pragma unroll
                for (int r = 0; r < 8; r++)
                    st_async_b32(rs[wb][r], hb32, rmb[wb][r]);
            } else if (tid < 64) {
                const int ft = tid - 32;
                // publish h[s-1] to L2 + helper signal — OFF the critical path
                // (hbuf[sb] = h[s-1] proven complete by the mbarrier wait)
                if (s > 0) {
                    __stcg(hgl + (size_t)(s - 1) * HD + c * 32 + ft,
                           hbuf[sb][c * 32 + ft]);
                    __syncwarp();
                    if (ft == 0 && layer == 0) rel_add(cnt);
                }
                // prefetch zbuf for step u = s+1
                if (s + 1 < TT) {
                    const int u = s + 1;
                    if (layer == 1) {
                        if (ft == 0) {
                            unsigned tgt = 16u * (unsigned)((u >> 1) + 1);
                            while (acq_ld(&g_cntzx[d][u & 1]) < tgt) { }
                        }
                        __syncwarp();
                    }
                    #pragma unroll
                    for (int gg = 0; gg < 4; gg++)
                        zbuf[u & 1][gg * 32 + ft] =
                            __ldcg(zxs + (size_t)u * 1024 + gg * 256 + c * 32 + ft);
                }
            }
        }
        // post-loop: fetch warp waits for the final pushes (h[TT-1] -> buffer 0)
        // and publishes them to L2
        if (tid >= 32 && tid < 64) {
            const int ft = tid - 32;
            mbar_wait_parity(mloc[0], ph[0]);
            __stcg(hgl + (size_t)(TT - 1) * HD + c * 32 + ft,
                   hbuf[TT & 1][c * 32 + ft]);
            __syncwarp();
            if (ft == 0 && layer == 0) rel_add(cnt);
        }
        cluster_sync_asm();    // keep SMEM alive for in-flight peer stores
    } else {
        // ===== helper CTAs: zx1 = h0 @ W1[0:256] + b1, parity-decomposed ====
        const int hix = bid - 32;          // 0..63
        const int d   = hix >> 5;          // direction
        const int pg  = (hix & 31) >> 4;   // step parity group (0=even,1=odd)
        const int hc  = hix & 15;          // 64-col block
        const float* __restrict__ W    = d ? Wb1 : Wf1;
        const float* __restrict__ bias = d ? bb1 : bf1;
        const int p = tid >> 6;            // K quarter (64 rows of W1[0:256])
        const int l = tid & 63;            // col (64 per CTA)
        const int col = hc * 64 + l;

        float w[64];
        #pragma unroll
        for (int i = 0; i < 64; i++)
            w[i] = W[(size_t)(p * 64 + i) * 1024 + col];
        const float bb = (tid < 64) ? bias[hc * 64 + tid] : 0.0f;

        float* hs  = &hbuf[0][0];          // reuse engine smem
        float* red = &redb[0][0];
        unsigned* cnt0d  = &g_csync[d];    // L0 engine counter for this dir
        unsigned* cntzxd = &g_cntzx[d][pg];
        const int koff = p * 64;

        for (int k = 0; k < TT / 2; k++) {
            const int s = 2 * k + pg;
            if (tid == 0) {
                unsigned tgt = 8u * (unsigned)(s + 1);   // 8 L0 CTAs per dir
                while (acq_ld(cnt0d) < tgt) { }
            }
            __syncthreads();
            hs[tid] = __ldcg(&g_h0[d][s][tid]);
            __syncthreads();

            float acc = 0.0f;
            #pragma unroll
            for (int i = 0; i < 64; i += 4) {
                float4 h4 = *(const float4*)&hs[koff + i];
                acc += w[i] * h4.x; acc += w[i + 1] * h4.y;
                acc += w[i + 2] * h4.z; acc += w[i + 3] * h4.w;
            }
            red[tid] = acc;
            __syncthreads();
            if (tid < 64) {
                float z = bb + red[tid] + red[64 + tid] + red[128 + tid] + red[192 + tid];
                __stcg(&g_zx1[d][s][hc * 64 + tid], z);
            }
            __syncthreads();               // all 64 stores issued before signal
            if (tid == 0) rel_add(cntzxd); // counter hits 16*(k+1) per (d,pg)
        }
    }
}

// ---------------- Phase C: final dense ---------------------------------------
__global__ void phaseC(const float* __restrict__ Wd, const float* __restrict__ bd,
                       float* __restrict__ out)
{
    const int chunk = blockIdx.x;
    const int o = threadIdx.x;
    __shared__ float hsm[8][512];
    for (int i = threadIdx.x; i < 8 * 512; i += 128) {
        int t8 = i >> 9, k = i & 511;
        int t = chunk * 8 + t8;
        hsm[t8][k] = (k < 256) ? g_h1[0][t][k] : g_h1[1][TT - 1 - t][k - 256];
    }
    __syncthreads();
    float b = bd[o];
    float acc[8];
    #pragma unroll
    for (int t8 = 0; t8 < 8; t8++) acc[t8] = b;
    #pragma unroll 8
    for (int k = 0; k < 512; k++) {
        float w = Wd[k * 128 + o];
        #pragma unroll
        for (int t8 = 0; t8 < 8; t8++) acc[t8] += hsm[t8][k] * w;
    }
    #pragma unroll
    for (int t8 = 0; t8 < 8; t8++) out[(chunk * 8 + t8) * 128 + o] = acc[t8];
}

// ---------------- launch -----------------------------------------------------
extern "C" void kernel_launch(void* const* d_in, const int* in_sizes, int n_in,
                              void* d_out, int out_size)
{
    (void)in_sizes; (void)n_in; (void)out_size;
    const float* x        = (const float*)d_in[0];
    const float* fw_state = (const float*)d_in[1];
    const float* bw_state = (const float*)d_in[2];
    const float* Wf0 = (const float*)d_in[3];
    const float* bf0 = (const float*)d_in[4];
    const float* Wf1 = (const float*)d_in[5];
    const float* bf1 = (const float*)d_in[6];
    const float* Wb0 = (const float*)d_in[7];
    const float* bb0 = (const float*)d_in[8];
    const float* Wb1 = (const float*)d_in[9];
    const float* bb1 = (const float*)d_in[10];
    const float* Wd  = (const float*)d_in[11];
    const float* bd  = (const float*)d_in[12];

    phaseA<<<256, 256>>>(x, Wf0, bf0, Wb0, bb0);

    cudaLaunchConfig_t cfg = {};
    cfg.gridDim  = dim3(96, 1, 1);
    cfg.blockDim = dim3(256, 1, 1);
    cfg.dynamicSmemBytes = 0;
    cfg.stream = 0;
    cudaLaunchAttribute attr[1];
    attr[0].id = cudaLaunchAttributeClusterDimension;
    attr[0].val.clusterDim.x = 8;
    attr[0].val.clusterDim.y = 1;
    attr[0].val.clusterDim.z = 1;
    cfg.attrs = attr;
    cfg.numAttrs = 1;
    cudaLaunchKernelEx(&cfg, phaseB, fw_state, bw_state,
                       Wf0, Wf1, bf1, Wb0, Wb1, bb1);

    phaseC<<<64, 128>>>(Wd, bd, (float*)d_out);
}